// round 4
// baseline (speedup 1.0000x reference)
#include <cuda_runtime.h>

// Fixed problem shape: U=80000, I=40000, N=120000, K=64, L=3, E=1e6
#define KF 64
#define NN 120000
#define EMAX 1000000
#define FULLMASK 0xffffffffu

typedef unsigned long long ull;

// --------------------------- device scratch (no allocs allowed) -------------
__device__ __align__(16) float g_x0[(size_t)NN * KF];
__device__ __align__(16) float g_x1[(size_t)NN * KF];
__device__ int g_deg[NN];
__device__ int g_start[NN + 1];
__device__ int g_cursor[NN];
__device__ int g_bsum[512];
__device__ int g_adj[2 * EMAX];

// =============================================================================
// init: e0 = l2norm(concat(Gu,Gi)) -> g_x0 ; out[n] = rowsum/256 ; deg = 0
// =============================================================================
__global__ __launch_bounds__(256) void init_kernel(
    const float* __restrict__ Gu, const float* __restrict__ Gi,
    float* __restrict__ out, int U, int Nn)
{
    int w = (blockIdx.x * blockDim.x + threadIdx.x) >> 5;
    if (w >= Nn) return;
    int lane = threadIdx.x & 31;
    const float* src = (w < U) ? (Gu + (size_t)w * KF) : (Gi + (size_t)(w - U) * KF);
    float2 v = ((const float2*)src)[lane];
    float ss = v.x * v.x + v.y * v.y;
    float sm = v.x + v.y;
#pragma unroll
    for (int off = 16; off >= 1; off >>= 1) {
        ss += __shfl_xor_sync(FULLMASK, ss, off);
        sm += __shfl_xor_sync(FULLMASK, sm, off);
    }
    float inv = 1.f / fmaxf(sqrtf(ss), 1e-12f);
    float2 o; o.x = v.x * inv; o.y = v.y * inv;
    ((float2*)(g_x0 + (size_t)w * KF))[lane] = o;
    if (lane == 0) { out[w] = sm * inv * (1.f / 256.f); g_deg[w] = 0; }
}

// =============================================================================
// CSR build: histogram -> 2-level exclusive scan -> bucket fill
// =============================================================================
__global__ __launch_bounds__(256) void hist_kernel(
    const int* __restrict__ eu, const int* __restrict__ ei, int E)
{
    int idx = blockIdx.x * blockDim.x + threadIdx.x;
    if (idx >= 2 * E) return;
    int dst = (idx < E) ? eu[idx] : ei[idx - E];
    atomicAdd(&g_deg[dst], 1);
}

__global__ __launch_bounds__(256) void scan1_kernel(int Nn)
{
    int i = blockIdx.x * 256 + threadIdx.x;
    int d = (i < Nn) ? g_deg[i] : 0;
    int lane = threadIdx.x & 31, wid = threadIdx.x >> 5;
    int v = d;
#pragma unroll
    for (int off = 1; off < 32; off <<= 1) {
        int t = __shfl_up_sync(FULLMASK, v, off);
        if (lane >= off) v += t;
    }
    __shared__ int wsum[8];
    if (lane == 31) wsum[wid] = v;
    __syncthreads();
    if (threadIdx.x < 8) {
        int wv = wsum[threadIdx.x];
#pragma unroll
        for (int off = 1; off < 8; off <<= 1) {
            int t = __shfl_up_sync(0xffu, wv, off);
            if ((int)threadIdx.x >= off) wv += t;
        }
        wsum[threadIdx.x] = wv;
    }
    __syncthreads();
    int woff = (wid > 0) ? wsum[wid - 1] : 0;
    if (i < Nn) g_start[i] = woff + v - d;
    if (threadIdx.x == 0) g_bsum[blockIdx.x] = wsum[7];
}

// warp-scan version: nb <= 512
__global__ __launch_bounds__(512) void scan2_kernel(int nb)
{
    int t = threadIdx.x;
    int lane = t & 31, wid = t >> 5;
    int d = (t < nb) ? g_bsum[t] : 0;
    int v = d;
#pragma unroll
    for (int off = 1; off < 32; off <<= 1) {
        int x = __shfl_up_sync(FULLMASK, v, off);
        if (lane >= off) v += x;
    }
    __shared__ int wsum[16];
    if (lane == 31) wsum[wid] = v;
    __syncthreads();
    if (t < 16) {
        int wv = wsum[t];
#pragma unroll
        for (int off = 1; off < 16; off <<= 1) {
            int x = __shfl_up_sync(0xffffu, wv, off);
            if (t >= off) wv += x;
        }
        wsum[t] = wv;
    }
    __syncthreads();
    int woff = (wid > 0) ? wsum[wid - 1] : 0;
    if (t < nb) g_bsum[t] = woff + v - d;  // exclusive
}

__global__ __launch_bounds__(256) void scan3_kernel(int Nn, int twoE)
{
    int i = blockIdx.x * 256 + threadIdx.x;
    if (i < Nn) {
        int st = g_start[i] + g_bsum[blockIdx.x];
        g_start[i] = st;
        g_cursor[i] = st;
    }
    if (i == 0) g_start[Nn] = twoE;
}

__global__ __launch_bounds__(256) void fill_kernel(
    const int* __restrict__ eu, const int* __restrict__ ei, int E)
{
    int idx = blockIdx.x * blockDim.x + threadIdx.x;
    if (idx >= 2 * E) return;
    int dst, src;
    if (idx < E) { dst = eu[idx]; src = ei[idx]; }
    else         { dst = ei[idx - E]; src = eu[idx - E]; }
    int pos = atomicAdd(&g_cursor[dst], 1);
    g_adj[pos] = src;
}

// =============================================================================
// Fused layer v2: CSR gather -> (s,p)-packed staging -> f32x2 dual-GEMM with
// lanes = (W1-term, W2-term), h = lo+hi -> leaky_relu -> l2norm -> out.
// Block = 128 threads, 64 nodes. Thread (jt in [0,8), g in [0,16)):
//   owns 8 strided features {jt, jt+8, ..., jt+56} x 4 nodes {4g..4g+3}.
// smem: sW12[k][j] = (W1[k][j], W2[k][j]); sSP[node][k] = (s_k, p_k).
// PITCH = 132 floats (528 B) -> 16B-aligned rows for float4 stores.
// =============================================================================
#define FMA2(d, a, b) asm("fma.rn.f32x2 %0, %1, %2, %0;" : "+l"(d) : "l"(a), "l"(b))

__device__ __forceinline__ float2 unpack2(ull v)
{
    float2 r;
    asm("mov.b64 {%0, %1}, %2;" : "=f"(r.x), "=f"(r.y) : "l"(v));
    return r;
}

#define PITCH 132                 // floats per row (128 data + 4 pad); 528B, 16B-aligned
#define SM_W12 0                  // 64 * PITCH floats
#define SM_SP  (64 * PITCH)       // 64 * PITCH floats
#define LAYER_SMEM_FLOATS (2 * 64 * PITCH)
#define LAYER_SMEM_BYTES  (LAYER_SMEM_FLOATS * 4)

__global__ __launch_bounds__(128, 3) void layer_kernel(
    const float* __restrict__ xin, float* __restrict__ xout,
    const float* __restrict__ W1, const float* __restrict__ b1,
    const float* __restrict__ W2, const float* __restrict__ b2,
    float* __restrict__ out)
{
    extern __shared__ float smem[];
    float* sW12 = smem + SM_W12;
    float* sSP  = smem + SM_SP;

    int t = threadIdx.x;

    // ---- stage interleaved weights: sW12[k*PITCH + 2j] = (W1[k][j], W2[k][j])
#pragma unroll
    for (int idx = t; idx < 4096; idx += 128) {
        int k = idx >> 6, j = idx & 63;
        float2 wv; wv.x = W1[idx]; wv.y = W2[idx];
        *(float2*)(sW12 + k * PITCH + 2 * j) = wv;
    }

    int base = blockIdx.x * 64;
    int w = t >> 5, lane = t & 31;
    const float2* xin2 = (const float2*)xin;

    // ---- gather: warp handles 16 nodes; lane owns k = 2*lane, 2*lane+1 ----
    for (int j = 0; j < 16; ++j) {
        int nl = w * 16 + j;
        int node = base + nl;
        int a  = g_start[node];
        int e0 = g_start[node + 1];
        float ax = 0.f, ay = 0.f;
        for (; a + 4 <= e0; a += 4) {
            int n0 = __ldg(g_adj + a);
            int n1 = __ldg(g_adj + a + 1);
            int n2 = __ldg(g_adj + a + 2);
            int n3 = __ldg(g_adj + a + 3);
            float2 v0 = __ldg(xin2 + (size_t)n0 * 32 + lane);
            float2 v1 = __ldg(xin2 + (size_t)n1 * 32 + lane);
            float2 v2 = __ldg(xin2 + (size_t)n2 * 32 + lane);
            float2 v3 = __ldg(xin2 + (size_t)n3 * 32 + lane);
            ax += (v0.x + v1.x) + (v2.x + v3.x);
            ay += (v0.y + v1.y) + (v2.y + v3.y);
        }
        int m = e0 - a;
        if (m > 0) { float2 v = __ldg(xin2 + (size_t)__ldg(g_adj + a)     * 32 + lane); ax += v.x; ay += v.y; }
        if (m > 1) { float2 v = __ldg(xin2 + (size_t)__ldg(g_adj + a + 1) * 32 + lane); ax += v.x; ay += v.y; }
        if (m > 2) { float2 v = __ldg(xin2 + (size_t)__ldg(g_adj + a + 2) * 32 + lane); ax += v.x; ay += v.y; }

        float2 xv = __ldg(xin2 + (size_t)node * 32 + lane);
        // (s,p) for k=2*lane and k=2*lane+1, stored contiguously
        float4 sp;
        sp.x = ax + xv.x; sp.y = ax * xv.x;
        sp.z = ay + xv.y; sp.w = ay * xv.y;
        *(float4*)(sSP + nl * PITCH + lane * 4) = sp;
    }
    __syncthreads();

    // ---- dual GEMM: acc.lo = sum s*W1, acc.hi = sum p*W2 ----
    int jt = t & 7;       // feature lane: features jt + 8*fi
    int g  = t >> 3;      // node group: nodes 4g..4g+3

    ull acc[8][4];
#pragma unroll
    for (int fi = 0; fi < 8; ++fi)
#pragma unroll
        for (int n = 0; n < 4; ++n)
            acc[fi][n] = 0ull;

    const float* sp0 = sSP + (g * 4 + 0) * PITCH;
    const float* sp1 = sSP + (g * 4 + 1) * PITCH;
    const float* sp2 = sSP + (g * 4 + 2) * PITCH;
    const float* sp3 = sSP + (g * 4 + 3) * PITCH;
    const float* wr  = sW12 + 2 * jt;

#pragma unroll 2
    for (int k = 0; k < 64; ++k) {
        ull spv0 = *(const ull*)(sp0 + 2 * k);
        ull spv1 = *(const ull*)(sp1 + 2 * k);
        ull spv2 = *(const ull*)(sp2 + 2 * k);
        ull spv3 = *(const ull*)(sp3 + 2 * k);
        const float* wk = wr + k * PITCH;
#pragma unroll
        for (int fi = 0; fi < 8; ++fi) {
            ull wv = *(const ull*)(wk + 16 * fi);
            FMA2(acc[fi][0], spv0, wv);
            FMA2(acc[fi][1], spv1, wv);
            FMA2(acc[fi][2], spv2, wv);
            FMA2(acc[fi][3], spv3, wv);
        }
    }

    // ---- epilogue: h = lo+hi+bias -> leaky -> l2norm (8-lane group) ----
#pragma unroll
    for (int n = 0; n < 4; ++n) {
        int node = base + g * 4 + n;
        float h[8];
        float ss = 0.f, sm = 0.f;
#pragma unroll
        for (int fi = 0; fi < 8; ++fi) {
            int f = jt + 8 * fi;
            float2 ab = unpack2(acc[fi][n]);
            float v = ab.x + ab.y + __ldg(b1 + f) + __ldg(b2 + f);
            v = v > 0.f ? v : 0.01f * v;
            h[fi] = v;
            ss += v * v;
            sm += v;
        }
#pragma unroll
        for (int off = 4; off >= 1; off >>= 1) {   // reduce over 8 jt lanes
            ss += __shfl_xor_sync(FULLMASK, ss, off);
            sm += __shfl_xor_sync(FULLMASK, sm, off);
        }
        float inv = 1.f / fmaxf(sqrtf(ss), 1e-12f);
        float* xo = xout + (size_t)node * KF + jt;
#pragma unroll
        for (int fi = 0; fi < 8; ++fi)
            xo[8 * fi] = h[fi] * inv;
        if (jt == 0) out[node] += sm * inv * (1.f / 256.f);
    }
}

// =============================================================================
// launch: init -> CSR build -> 3 x fused layer (ping-pong x buffers)
// =============================================================================
extern "C" void kernel_launch(void* const* d_in, const int* in_sizes, int n_in,
                              void* d_out, int out_size)
{
    const float* Gu = (const float*)d_in[0];
    const float* Gi = (const float*)d_in[1];
    const float* W1 = (const float*)d_in[2];
    const float* b1 = (const float*)d_in[3];
    const float* W2 = (const float*)d_in[4];
    const float* b2 = (const float*)d_in[5];
    const int*   ed = (const int*)d_in[6];
    float* out = (float*)d_out;

    int U  = in_sizes[0] / KF;
    int I  = in_sizes[1] / KF;
    int Nn = U + I;
    int L  = in_sizes[3] / KF;
    int E  = in_sizes[6] / 2;
    int twoE = 2 * E;

    const int* eu = ed;
    const int* ei = ed + E;

    cudaFuncSetAttribute(layer_kernel,
                         cudaFuncAttributeMaxDynamicSharedMemorySize,
                         LAYER_SMEM_BYTES);

    float *xa, *xb;
    cudaGetSymbolAddress((void**)&xa, g_x0);
    cudaGetSymbolAddress((void**)&xb, g_x1);

    int initBlocks = (Nn * 32 + 255) / 256;
    init_kernel<<<initBlocks, 256>>>(Gu, Gi, out, U, Nn);

    int eBlocks = (twoE + 255) / 256;
    int nBlocks = (Nn + 255) / 256;
    hist_kernel<<<eBlocks, 256>>>(eu, ei, E);
    scan1_kernel<<<nBlocks, 256>>>(Nn);
    scan2_kernel<<<1, 512>>>(nBlocks);
    scan3_kernel<<<nBlocks, 256>>>(Nn, twoE);
    fill_kernel<<<eBlocks, 256>>>(eu, ei, E);

    int lBlocks = Nn / 64;  // 1875
    for (int l = 0; l < L; ++l) {
        layer_kernel<<<lBlocks, 128, LAYER_SMEM_BYTES>>>(
            xa, xb,
            W1 + (size_t)l * KF * KF, b1 + (size_t)l * KF,
            W2 + (size_t)l * KF * KF, b2 + (size_t)l * KF,
            out);
        float* tmp = xa; xa = xb; xb = tmp;
    }
}

// round 5
// speedup vs baseline: 1.1757x; 1.1757x over previous
#include <cuda_runtime.h>

// Fixed problem shape: U=80000, I=40000, N=120000, K=64, L=3, E=1e6
#define KF 64
#define NN 120000
#define EMAX 1000000
#define FULLMASK 0xffffffffu

typedef unsigned long long ull;

// --------------------------- device scratch (no allocs allowed) -------------
// +1 row: index Nn is an all-zero pad row (in both ping-pong buffers)
__device__ __align__(16) float g_x0[(size_t)(NN + 1) * KF];
__device__ __align__(16) float g_x1[(size_t)(NN + 1) * KF];
__device__ int g_deg[NN];
__device__ int g_start[NN + 2];
__device__ int g_cursor[NN + 1];
__device__ int g_bsum[512];
__device__ int g_adj[2 * EMAX + 8 * NN];   // padded CSR

// =============================================================================
// init: e0 = l2norm(concat(Gu,Gi)) -> g_x0 ; out[n] = rowsum/256 ; deg = 0
// extra warp (w == Nn) zeroes the pad row in both buffers
// =============================================================================
__global__ __launch_bounds__(256) void init_kernel(
    const float* __restrict__ Gu, const float* __restrict__ Gi,
    float* __restrict__ out, int U, int Nn)
{
    int w = (blockIdx.x * blockDim.x + threadIdx.x) >> 5;
    int lane = threadIdx.x & 31;
    if (w > Nn) return;
    if (w == Nn) {
        float2 z; z.x = 0.f; z.y = 0.f;
        ((float2*)(g_x0 + (size_t)Nn * KF))[lane] = z;
        ((float2*)(g_x1 + (size_t)Nn * KF))[lane] = z;
        return;
    }
    const float* src = (w < U) ? (Gu + (size_t)w * KF) : (Gi + (size_t)(w - U) * KF);
    float2 v = ((const float2*)src)[lane];
    float ss = v.x * v.x + v.y * v.y;
    float sm = v.x + v.y;
#pragma unroll
    for (int off = 16; off >= 1; off >>= 1) {
        ss += __shfl_xor_sync(FULLMASK, ss, off);
        sm += __shfl_xor_sync(FULLMASK, sm, off);
    }
    float inv = 1.f / fmaxf(sqrtf(ss), 1e-12f);
    float2 o; o.x = v.x * inv; o.y = v.y * inv;
    ((float2*)(g_x0 + (size_t)w * KF))[lane] = o;
    if (lane == 0) { out[w] = sm * inv * (1.f / 256.f); g_deg[w] = 0; }
}

// =============================================================================
// CSR build (padded): histogram -> scan of padded degrees -> fill -> pad
// =============================================================================
__global__ __launch_bounds__(256) void hist_kernel(
    const int* __restrict__ eu, const int* __restrict__ ei, int E)
{
    int idx = blockIdx.x * blockDim.x + threadIdx.x;
    if (idx >= 2 * E) return;
    int dst = (idx < E) ? eu[idx] : ei[idx - E];
    atomicAdd(&g_deg[dst], 1);
}

// scan over Nn+1 virtual elements of padded degree (element Nn = 0)
__global__ __launch_bounds__(256) void scan1_kernel(int Nn)
{
    int i = blockIdx.x * 256 + threadIdx.x;
    int d = (i < Nn) ? ((g_deg[i] + 7) & ~7) : 0;
    int lane = threadIdx.x & 31, wid = threadIdx.x >> 5;
    int v = d;
#pragma unroll
    for (int off = 1; off < 32; off <<= 1) {
        int t = __shfl_up_sync(FULLMASK, v, off);
        if (lane >= off) v += t;
    }
    __shared__ int wsum[8];
    if (lane == 31) wsum[wid] = v;
    __syncthreads();
    if (threadIdx.x < 8) {
        int wv = wsum[threadIdx.x];
#pragma unroll
        for (int off = 1; off < 8; off <<= 1) {
            int t = __shfl_up_sync(0xffu, wv, off);
            if ((int)threadIdx.x >= off) wv += t;
        }
        wsum[threadIdx.x] = wv;
    }
    __syncthreads();
    int woff = (wid > 0) ? wsum[wid - 1] : 0;
    if (i <= Nn) g_start[i] = woff + v - d;
    if (threadIdx.x == 0) g_bsum[blockIdx.x] = wsum[7];
}

__global__ __launch_bounds__(512) void scan2_kernel(int nb)
{
    int t = threadIdx.x;
    int lane = t & 31, wid = t >> 5;
    int d = (t < nb) ? g_bsum[t] : 0;
    int v = d;
#pragma unroll
    for (int off = 1; off < 32; off <<= 1) {
        int x = __shfl_up_sync(FULLMASK, v, off);
        if (lane >= off) v += x;
    }
    __shared__ int wsum[16];
    if (lane == 31) wsum[wid] = v;
    __syncthreads();
    if (t < 16) {
        int wv = wsum[t];
#pragma unroll
        for (int off = 1; off < 16; off <<= 1) {
            int x = __shfl_up_sync(0xffffu, wv, off);
            if (t >= off) wv += x;
        }
        wsum[t] = wv;
    }
    __syncthreads();
    int woff = (wid > 0) ? wsum[wid - 1] : 0;
    if (t < nb) g_bsum[t] = woff + v - d;  // exclusive
}

__global__ __launch_bounds__(256) void scan3_kernel(int Nn)
{
    int i = blockIdx.x * 256 + threadIdx.x;
    if (i <= Nn) {
        int st = g_start[i] + g_bsum[blockIdx.x];
        g_start[i] = st;
        if (i < Nn) g_cursor[i] = st;
    }
}

__global__ __launch_bounds__(256) void fill_kernel(
    const int* __restrict__ eu, const int* __restrict__ ei, int E)
{
    int idx = blockIdx.x * blockDim.x + threadIdx.x;
    if (idx >= 2 * E) return;
    int dst, src;
    if (idx < E) { dst = eu[idx]; src = ei[idx]; }
    else         { dst = ei[idx - E]; src = eu[idx - E]; }
    int pos = atomicAdd(&g_cursor[dst], 1);
    g_adj[pos] = src;
}

// fill the padded tail of each node's segment with the zero-row index Nn
__global__ __launch_bounds__(256) void pad_kernel(int Nn)
{
    int i = blockIdx.x * 256 + threadIdx.x;
    if (i >= Nn) return;
    int en = g_start[i + 1];
    for (int p = g_start[i] + g_deg[i]; p < en; ++p) g_adj[p] = Nn;
}

// =============================================================================
// Fused layer: padded CSR gather (unroll-8, adj prefetch) -> (s,p) staging ->
// f32x2 dual-GEMM (lanes = W1-term/W2-term) -> leaky -> l2norm -> out.
// Block = 128 threads, 64 nodes, 3 blocks/SM.
// =============================================================================
#define FMA2(d, a, b) asm("fma.rn.f32x2 %0, %1, %2, %0;" : "+l"(d) : "l"(a), "l"(b))

__device__ __forceinline__ float2 unpack2(ull v)
{
    float2 r;
    asm("mov.b64 {%0, %1}, %2;" : "=f"(r.x), "=f"(r.y) : "l"(v));
    return r;
}

#define PITCH 132                 // floats per row (128 data + 4 pad); 528B, 16B-aligned
#define SM_W12 0
#define SM_SP  (64 * PITCH)
#define LAYER_SMEM_FLOATS (2 * 64 * PITCH)
#define LAYER_SMEM_BYTES  (LAYER_SMEM_FLOATS * 4)

__global__ __launch_bounds__(128, 3) void layer_kernel(
    const float* __restrict__ xin, float* __restrict__ xout,
    const float* __restrict__ W1, const float* __restrict__ b1,
    const float* __restrict__ W2, const float* __restrict__ b2,
    float* __restrict__ out)
{
    extern __shared__ float smem[];
    float* sW12 = smem + SM_W12;
    float* sSP  = smem + SM_SP;

    int t = threadIdx.x;

    // stage interleaved weights: sW12[k*PITCH + 2j] = (W1[k][j], W2[k][j])
#pragma unroll
    for (int idx = t; idx < 4096; idx += 128) {
        int k = idx >> 6, j = idx & 63;
        float2 wv; wv.x = W1[idx]; wv.y = W2[idx];
        *(float2*)(sW12 + k * PITCH + 2 * j) = wv;
    }

    int base = blockIdx.x * 64;
    int w = t >> 5, lane = t & 31;
    const float2* xin2 = (const float2*)xin;

    // ---- gather: warp handles 16 nodes; padded segments, unroll 8 ----
    for (int j = 0; j < 16; ++j) {
        int nl = w * 16 + j;
        int node = base + nl;
        int a    = g_start[node];
        int pend = g_start[node + 1];
        float ax = 0.f, ay = 0.f;
        if (a < pend) {
            int4 A = *(const int4*)(g_adj + a);
            int4 B = *(const int4*)(g_adj + a + 4);
            for (a += 8; a < pend; a += 8) {
                int4 An = *(const int4*)(g_adj + a);
                int4 Bn = *(const int4*)(g_adj + a + 4);
                float2 v0 = __ldg(xin2 + (size_t)A.x * 32 + lane);
                float2 v1 = __ldg(xin2 + (size_t)A.y * 32 + lane);
                float2 v2 = __ldg(xin2 + (size_t)A.z * 32 + lane);
                float2 v3 = __ldg(xin2 + (size_t)A.w * 32 + lane);
                float2 v4 = __ldg(xin2 + (size_t)B.x * 32 + lane);
                float2 v5 = __ldg(xin2 + (size_t)B.y * 32 + lane);
                float2 v6 = __ldg(xin2 + (size_t)B.z * 32 + lane);
                float2 v7 = __ldg(xin2 + (size_t)B.w * 32 + lane);
                ax += ((v0.x + v1.x) + (v2.x + v3.x)) + ((v4.x + v5.x) + (v6.x + v7.x));
                ay += ((v0.y + v1.y) + (v2.y + v3.y)) + ((v4.y + v5.y) + (v6.y + v7.y));
                A = An; B = Bn;
            }
            float2 v0 = __ldg(xin2 + (size_t)A.x * 32 + lane);
            float2 v1 = __ldg(xin2 + (size_t)A.y * 32 + lane);
            float2 v2 = __ldg(xin2 + (size_t)A.z * 32 + lane);
            float2 v3 = __ldg(xin2 + (size_t)A.w * 32 + lane);
            float2 v4 = __ldg(xin2 + (size_t)B.x * 32 + lane);
            float2 v5 = __ldg(xin2 + (size_t)B.y * 32 + lane);
            float2 v6 = __ldg(xin2 + (size_t)B.z * 32 + lane);
            float2 v7 = __ldg(xin2 + (size_t)B.w * 32 + lane);
            ax += ((v0.x + v1.x) + (v2.x + v3.x)) + ((v4.x + v5.x) + (v6.x + v7.x));
            ay += ((v0.y + v1.y) + (v2.y + v3.y)) + ((v4.y + v5.y) + (v6.y + v7.y));
        }

        float2 xv = __ldg(xin2 + (size_t)node * 32 + lane);
        float4 sp;                    // (s,p) for k=2*lane, 2*lane+1
        sp.x = ax + xv.x; sp.y = ax * xv.x;
        sp.z = ay + xv.y; sp.w = ay * xv.y;
        *(float4*)(sSP + nl * PITCH + lane * 4) = sp;
    }
    __syncthreads();

    // ---- dual GEMM: acc.lo = sum s*W1, acc.hi = sum p*W2 ----
    int jt = t & 7;       // feature lane: features jt + 8*fi
    int g  = t >> 3;      // node group: nodes 4g..4g+3

    ull acc[8][4];
#pragma unroll
    for (int fi = 0; fi < 8; ++fi)
#pragma unroll
        for (int n = 0; n < 4; ++n)
            acc[fi][n] = 0ull;

    const float* sp0 = sSP + (g * 4 + 0) * PITCH;
    const float* sp1 = sSP + (g * 4 + 1) * PITCH;
    const float* sp2 = sSP + (g * 4 + 2) * PITCH;
    const float* sp3 = sSP + (g * 4 + 3) * PITCH;
    const float* wr  = sW12 + 2 * jt;

#pragma unroll 2
    for (int k = 0; k < 64; ++k) {
        ull spv0 = *(const ull*)(sp0 + 2 * k);
        ull spv1 = *(const ull*)(sp1 + 2 * k);
        ull spv2 = *(const ull*)(sp2 + 2 * k);
        ull spv3 = *(const ull*)(sp3 + 2 * k);
        const float* wk = wr + k * PITCH;
#pragma unroll
        for (int fi = 0; fi < 8; ++fi) {
            ull wv = *(const ull*)(wk + 16 * fi);
            FMA2(acc[fi][0], spv0, wv);
            FMA2(acc[fi][1], spv1, wv);
            FMA2(acc[fi][2], spv2, wv);
            FMA2(acc[fi][3], spv3, wv);
        }
    }

    // ---- epilogue ----
#pragma unroll
    for (int n = 0; n < 4; ++n) {
        int node = base + g * 4 + n;
        float h[8];
        float ss = 0.f, sm = 0.f;
#pragma unroll
        for (int fi = 0; fi < 8; ++fi) {
            int f = jt + 8 * fi;
            float2 ab = unpack2(acc[fi][n]);
            float v = ab.x + ab.y + __ldg(b1 + f) + __ldg(b2 + f);
            v = v > 0.f ? v : 0.01f * v;
            h[fi] = v;
            ss += v * v;
            sm += v;
        }
#pragma unroll
        for (int off = 4; off >= 1; off >>= 1) {
            ss += __shfl_xor_sync(FULLMASK, ss, off);
            sm += __shfl_xor_sync(FULLMASK, sm, off);
        }
        float inv = 1.f / fmaxf(sqrtf(ss), 1e-12f);
        float* xo = xout + (size_t)node * KF + jt;
#pragma unroll
        for (int fi = 0; fi < 8; ++fi)
            xo[8 * fi] = h[fi] * inv;
        if (jt == 0) out[node] += sm * inv * (1.f / 256.f);
    }
}

// =============================================================================
// launch
// =============================================================================
extern "C" void kernel_launch(void* const* d_in, const int* in_sizes, int n_in,
                              void* d_out, int out_size)
{
    const float* Gu = (const float*)d_in[0];
    const float* Gi = (const float*)d_in[1];
    const float* W1 = (const float*)d_in[2];
    const float* b1 = (const float*)d_in[3];
    const float* W2 = (const float*)d_in[4];
    const float* b2 = (const float*)d_in[5];
    const int*   ed = (const int*)d_in[6];
    float* out = (float*)d_out;

    int U  = in_sizes[0] / KF;
    int I  = in_sizes[1] / KF;
    int Nn = U + I;
    int L  = in_sizes[3] / KF;
    int E  = in_sizes[6] / 2;
    int twoE = 2 * E;

    const int* eu = ed;
    const int* ei = ed + E;

    cudaFuncSetAttribute(layer_kernel,
                         cudaFuncAttributeMaxDynamicSharedMemorySize,
                         LAYER_SMEM_BYTES);

    float *xa, *xb;
    cudaGetSymbolAddress((void**)&xa, g_x0);
    cudaGetSymbolAddress((void**)&xb, g_x1);

    int initBlocks = ((Nn + 1) * 32 + 255) / 256;
    init_kernel<<<initBlocks, 256>>>(Gu, Gi, out, U, Nn);

    int eBlocks = (twoE + 255) / 256;
    int nBlocks  = (Nn + 256) / 256;   // covers Nn+1 elements
    int nBlocks0 = (Nn + 255) / 256;   // covers Nn elements
    hist_kernel<<<eBlocks, 256>>>(eu, ei, E);
    scan1_kernel<<<nBlocks, 256>>>(Nn);
    scan2_kernel<<<1, 512>>>(nBlocks);
    scan3_kernel<<<nBlocks, 256>>>(Nn);
    fill_kernel<<<eBlocks, 256>>>(eu, ei, E);
    pad_kernel<<<nBlocks0, 256>>>(Nn);

    int lBlocks = Nn / 64;  // 1875
    for (int l = 0; l < L; ++l) {
        layer_kernel<<<lBlocks, 128, LAYER_SMEM_BYTES>>>(
            xa, xb,
            W1 + (size_t)l * KF * KF, b1 + (size_t)l * KF,
            W2 + (size_t)l * KF * KF, b2 + (size_t)l * KF,
            out);
        float* tmp = xa; xa = xb; xb = tmp;
    }
}

// round 6
// speedup vs baseline: 1.4662x; 1.2470x over previous
#include <cuda_runtime.h>

// Fixed problem shape: U=80000, I=40000, N=120000, K=64, L=3, E=1e6
#define KF 64
#define NN 120000
#define EMAX 1000000
#define FULLMASK 0xffffffffu

typedef unsigned long long ull;

// --------------------------- device scratch (no allocs allowed) -------------
// +1 row: index Nn is an all-zero pad row (in both ping-pong buffers)
__device__ __align__(16) float g_x0[(size_t)(NN + 1) * KF];
__device__ __align__(16) float g_x1[(size_t)(NN + 1) * KF];
__device__ __align__(16) float g_side[(size_t)NN * KF];
__device__ int g_deg[NN];
__device__ int g_start[NN + 2];
__device__ int g_cursor[NN + 1];
__device__ int g_bsum[512];
__device__ int g_adj[2 * EMAX + 4 * NN];   // CSR padded to multiples of 4

// =============================================================================
// init: e0 = l2norm(concat(Gu,Gi)) -> g_x0 ; out[n] = rowsum/256 ; deg = 0
// extra warp (w == Nn) zeroes the pad row in both ping-pong buffers
// =============================================================================
__global__ __launch_bounds__(256) void init_kernel(
    const float* __restrict__ Gu, const float* __restrict__ Gi,
    float* __restrict__ out, int U, int Nn)
{
    int w = (blockIdx.x * blockDim.x + threadIdx.x) >> 5;
    int lane = threadIdx.x & 31;
    if (w > Nn) return;
    if (w == Nn) {
        float2 z; z.x = 0.f; z.y = 0.f;
        ((float2*)(g_x0 + (size_t)Nn * KF))[lane] = z;
        ((float2*)(g_x1 + (size_t)Nn * KF))[lane] = z;
        return;
    }
    const float* src = (w < U) ? (Gu + (size_t)w * KF) : (Gi + (size_t)(w - U) * KF);
    float2 v = ((const float2*)src)[lane];
    float ss = v.x * v.x + v.y * v.y;
    float sm = v.x + v.y;
#pragma unroll
    for (int off = 16; off >= 1; off >>= 1) {
        ss += __shfl_xor_sync(FULLMASK, ss, off);
        sm += __shfl_xor_sync(FULLMASK, sm, off);
    }
    float inv = 1.f / fmaxf(sqrtf(ss), 1e-12f);
    float2 o; o.x = v.x * inv; o.y = v.y * inv;
    ((float2*)(g_x0 + (size_t)w * KF))[lane] = o;
    if (lane == 0) { out[w] = sm * inv * (1.f / 256.f); g_deg[w] = 0; }
}

// =============================================================================
// CSR build (padded to 4): histogram -> scan of padded degrees -> fill
// (tail padding fused into scan3: pad slots are never touched by fill)
// =============================================================================
__global__ __launch_bounds__(256) void hist_kernel(
    const int* __restrict__ eu, const int* __restrict__ ei, int E)
{
    int idx = blockIdx.x * blockDim.x + threadIdx.x;
    if (idx >= 2 * E) return;
    int dst = (idx < E) ? eu[idx] : ei[idx - E];
    atomicAdd(&g_deg[dst], 1);
}

// scan over Nn+1 virtual elements of padded degree (element Nn = 0)
__global__ __launch_bounds__(256) void scan1_kernel(int Nn)
{
    int i = blockIdx.x * 256 + threadIdx.x;
    int d = (i < Nn) ? ((g_deg[i] + 3) & ~3) : 0;
    int lane = threadIdx.x & 31, wid = threadIdx.x >> 5;
    int v = d;
#pragma unroll
    for (int off = 1; off < 32; off <<= 1) {
        int t = __shfl_up_sync(FULLMASK, v, off);
        if (lane >= off) v += t;
    }
    __shared__ int wsum[8];
    if (lane == 31) wsum[wid] = v;
    __syncthreads();
    if (threadIdx.x < 8) {
        int wv = wsum[threadIdx.x];
#pragma unroll
        for (int off = 1; off < 8; off <<= 1) {
            int t = __shfl_up_sync(0xffu, wv, off);
            if ((int)threadIdx.x >= off) wv += t;
        }
        wsum[threadIdx.x] = wv;
    }
    __syncthreads();
    int woff = (wid > 0) ? wsum[wid - 1] : 0;
    if (i <= Nn) g_start[i] = woff + v - d;
    if (threadIdx.x == 0) g_bsum[blockIdx.x] = wsum[7];
}

__global__ __launch_bounds__(512) void scan2_kernel(int nb)
{
    int t = threadIdx.x;
    int lane = t & 31, wid = t >> 5;
    int d = (t < nb) ? g_bsum[t] : 0;
    int v = d;
#pragma unroll
    for (int off = 1; off < 32; off <<= 1) {
        int x = __shfl_up_sync(FULLMASK, v, off);
        if (lane >= off) v += x;
    }
    __shared__ int wsum[16];
    if (lane == 31) wsum[wid] = v;
    __syncthreads();
    if (t < 16) {
        int wv = wsum[t];
#pragma unroll
        for (int off = 1; off < 16; off <<= 1) {
            int x = __shfl_up_sync(0xffffu, wv, off);
            if (t >= off) wv += x;
        }
        wsum[t] = wv;
    }
    __syncthreads();
    int woff = (wid > 0) ? wsum[wid - 1] : 0;
    if (t < nb) g_bsum[t] = woff + v - d;  // exclusive
}

// finalize starts + cursors + write pad tails (disjoint from fill's slots)
__global__ __launch_bounds__(256) void scan3_kernel(int Nn)
{
    int i = blockIdx.x * 256 + threadIdx.x;
    if (i > Nn) return;
    int st = g_start[i] + g_bsum[blockIdx.x];
    g_start[i] = st;
    if (i < Nn) {
        g_cursor[i] = st;
        int d  = g_deg[i];
        int pd = (d + 3) & ~3;
        for (int p = d; p < pd; ++p) g_adj[st + p] = Nn;  // zero-row index
    }
}

__global__ __launch_bounds__(256) void fill_kernel(
    const int* __restrict__ eu, const int* __restrict__ ei, int E)
{
    int idx = blockIdx.x * blockDim.x + threadIdx.x;
    if (idx >= 2 * E) return;
    int dst, src;
    if (idx < E) { dst = eu[idx]; src = ei[idx]; }
    else         { dst = ei[idx - E]; src = eu[idx - E]; }
    int pos = atomicAdd(&g_cursor[dst], 1);
    g_adj[pos] = src;
}

// =============================================================================
// gather: side = A @ x. One warp per node, lane owns 2 features (float2).
// No smem, low regs -> high occupancy; 4 rows in flight per warp via int4
// adjacency prefetch. Segments are padded to 4 with the zero row.
// =============================================================================
__global__ __launch_bounds__(256) void gather_kernel(
    const float* __restrict__ xin, int Nn)
{
    int node = (blockIdx.x * blockDim.x + threadIdx.x) >> 5;
    if (node >= Nn) return;
    int lane = threadIdx.x & 31;
    const float2* xin2 = (const float2*)xin;

    int a    = __ldg(g_start + node);
    int pend = __ldg(g_start + node + 1);
    float ax = 0.f, ay = 0.f;
    if (a < pend) {
        int4 A = *(const int4*)(g_adj + a);
        for (a += 4; a < pend; a += 4) {
            int4 An = *(const int4*)(g_adj + a);
            float2 v0 = __ldg(xin2 + (size_t)A.x * 32 + lane);
            float2 v1 = __ldg(xin2 + (size_t)A.y * 32 + lane);
            float2 v2 = __ldg(xin2 + (size_t)A.z * 32 + lane);
            float2 v3 = __ldg(xin2 + (size_t)A.w * 32 + lane);
            ax += (v0.x + v1.x) + (v2.x + v3.x);
            ay += (v0.y + v1.y) + (v2.y + v3.y);
            A = An;
        }
        float2 v0 = __ldg(xin2 + (size_t)A.x * 32 + lane);
        float2 v1 = __ldg(xin2 + (size_t)A.y * 32 + lane);
        float2 v2 = __ldg(xin2 + (size_t)A.z * 32 + lane);
        float2 v3 = __ldg(xin2 + (size_t)A.w * 32 + lane);
        ax += (v0.x + v1.x) + (v2.x + v3.x);
        ay += (v0.y + v1.y) + (v2.y + v3.y);
    }
    float2 o; o.x = ax; o.y = ay;
    ((float2*)(g_side + (size_t)node * KF))[lane] = o;
}

// =============================================================================
// layer: stream side+x -> (s,p) smem staging -> f32x2 dual-GEMM
// (lanes = W1-term/W2-term) -> leaky -> l2norm -> xout, out accumulation.
// Block = 128 threads, 64 nodes, 3 blocks/SM.
// =============================================================================
#define FMA2(d, a, b) asm("fma.rn.f32x2 %0, %1, %2, %0;" : "+l"(d) : "l"(a), "l"(b))

__device__ __forceinline__ float2 unpack2(ull v)
{
    float2 r;
    asm("mov.b64 {%0, %1}, %2;" : "=f"(r.x), "=f"(r.y) : "l"(v));
    return r;
}

#define PITCH 132                 // floats per row (128 data + 4 pad); 528B, 16B-aligned
#define SM_W12 0
#define SM_SP  (64 * PITCH)
#define LAYER_SMEM_FLOATS (2 * 64 * PITCH)
#define LAYER_SMEM_BYTES  (LAYER_SMEM_FLOATS * 4)

__global__ __launch_bounds__(128, 3) void layer_kernel(
    const float* __restrict__ xin, float* __restrict__ xout,
    const float* __restrict__ W1, const float* __restrict__ b1,
    const float* __restrict__ W2, const float* __restrict__ b2,
    float* __restrict__ out)
{
    extern __shared__ float smem[];
    float* sW12 = smem + SM_W12;
    float* sSP  = smem + SM_SP;

    int t = threadIdx.x;

    // stage interleaved weights: sW12[k*PITCH + 2j] = (W1[k][j], W2[k][j])
#pragma unroll
    for (int idx = t; idx < 4096; idx += 128) {
        int k = idx >> 6, j = idx & 63;
        float2 wv; wv.x = W1[idx]; wv.y = W2[idx];
        *(float2*)(sW12 + k * PITCH + 2 * j) = wv;
    }

    int base = blockIdx.x * 64;
    int w = t >> 5, lane = t & 31;
    const float2* xin2  = (const float2*)xin;
    const float2* side2 = (const float2*)g_side;

    // ---- stage (s,p): warp handles 16 nodes, lane owns k = 2*lane, 2*lane+1
#pragma unroll 4
    for (int j = 0; j < 16; ++j) {
        int nl = w * 16 + j;
        int node = base + nl;
        float2 sv = __ldg(side2 + (size_t)node * 32 + lane);
        float2 xv = __ldg(xin2  + (size_t)node * 32 + lane);
        float4 sp;
        sp.x = sv.x + xv.x; sp.y = sv.x * xv.x;
        sp.z = sv.y + xv.y; sp.w = sv.y * xv.y;
        *(float4*)(sSP + nl * PITCH + lane * 4) = sp;
    }
    __syncthreads();

    // ---- dual GEMM: acc.lo = sum s*W1, acc.hi = sum p*W2 ----
    int jt = t & 7;       // feature lane: features jt + 8*fi
    int g  = t >> 3;      // node group: nodes 4g..4g+3

    ull acc[8][4];
#pragma unroll
    for (int fi = 0; fi < 8; ++fi)
#pragma unroll
        for (int n = 0; n < 4; ++n)
            acc[fi][n] = 0ull;

    const float* sp0 = sSP + (g * 4 + 0) * PITCH;
    const float* sp1 = sSP + (g * 4 + 1) * PITCH;
    const float* sp2 = sSP + (g * 4 + 2) * PITCH;
    const float* sp3 = sSP + (g * 4 + 3) * PITCH;
    const float* wr  = sW12 + 2 * jt;

#pragma unroll 2
    for (int k = 0; k < 64; ++k) {
        ull spv0 = *(const ull*)(sp0 + 2 * k);
        ull spv1 = *(const ull*)(sp1 + 2 * k);
        ull spv2 = *(const ull*)(sp2 + 2 * k);
        ull spv3 = *(const ull*)(sp3 + 2 * k);
        const float* wk = wr + k * PITCH;
#pragma unroll
        for (int fi = 0; fi < 8; ++fi) {
            ull wv = *(const ull*)(wk + 16 * fi);
            FMA2(acc[fi][0], spv0, wv);
            FMA2(acc[fi][1], spv1, wv);
            FMA2(acc[fi][2], spv2, wv);
            FMA2(acc[fi][3], spv3, wv);
        }
    }

    // ---- epilogue ----
#pragma unroll
    for (int n = 0; n < 4; ++n) {
        int node = base + g * 4 + n;
        float h[8];
        float ss = 0.f, sm = 0.f;
#pragma unroll
        for (int fi = 0; fi < 8; ++fi) {
            int f = jt + 8 * fi;
            float2 ab = unpack2(acc[fi][n]);
            float v = ab.x + ab.y + __ldg(b1 + f) + __ldg(b2 + f);
            v = v > 0.f ? v : 0.01f * v;
            h[fi] = v;
            ss += v * v;
            sm += v;
        }
#pragma unroll
        for (int off = 4; off >= 1; off >>= 1) {
            ss += __shfl_xor_sync(FULLMASK, ss, off);
            sm += __shfl_xor_sync(FULLMASK, sm, off);
        }
        float inv = 1.f / fmaxf(sqrtf(ss), 1e-12f);
        float* xo = xout + (size_t)node * KF + jt;
#pragma unroll
        for (int fi = 0; fi < 8; ++fi)
            xo[8 * fi] = h[fi] * inv;
        if (jt == 0) out[node] += sm * inv * (1.f / 256.f);
    }
}

// =============================================================================
// launch: init -> CSR build -> 3 x (gather -> layer), ping-pong x buffers
// =============================================================================
extern "C" void kernel_launch(void* const* d_in, const int* in_sizes, int n_in,
                              void* d_out, int out_size)
{
    const float* Gu = (const float*)d_in[0];
    const float* Gi = (const float*)d_in[1];
    const float* W1 = (const float*)d_in[2];
    const float* b1 = (const float*)d_in[3];
    const float* W2 = (const float*)d_in[4];
    const float* b2 = (const float*)d_in[5];
    const int*   ed = (const int*)d_in[6];
    float* out = (float*)d_out;

    int U  = in_sizes[0] / KF;
    int I  = in_sizes[1] / KF;
    int Nn = U + I;
    int L  = in_sizes[3] / KF;
    int E  = in_sizes[6] / 2;
    int twoE = 2 * E;

    const int* eu = ed;
    const int* ei = ed + E;

    cudaFuncSetAttribute(layer_kernel,
                         cudaFuncAttributeMaxDynamicSharedMemorySize,
                         LAYER_SMEM_BYTES);

    float *xa, *xb;
    cudaGetSymbolAddress((void**)&xa, g_x0);
    cudaGetSymbolAddress((void**)&xb, g_x1);

    int initBlocks = ((Nn + 1) * 32 + 255) / 256;
    init_kernel<<<initBlocks, 256>>>(Gu, Gi, out, U, Nn);

    int eBlocks = (twoE + 255) / 256;
    int nBlocks  = (Nn + 256) / 256;   // covers Nn+1 elements
    hist_kernel<<<eBlocks, 256>>>(eu, ei, E);
    scan1_kernel<<<nBlocks, 256>>>(Nn);
    scan2_kernel<<<1, 512>>>(nBlocks);
    scan3_kernel<<<nBlocks, 256>>>(Nn);
    fill_kernel<<<eBlocks, 256>>>(eu, ei, E);

    int gBlocks = (Nn * 32 + 255) / 256;
    int lBlocks = Nn / 64;  // 1875
    for (int l = 0; l < L; ++l) {
        gather_kernel<<<gBlocks, 256>>>(xa, Nn);
        layer_kernel<<<lBlocks, 128, LAYER_SMEM_BYTES>>>(
            xa, xb,
            W1 + (size_t)l * KF * KF, b1 + (size_t)l * KF,
            W2 + (size_t)l * KF * KF, b2 + (size_t)l * KF,
            out);
        float* tmp = xa; xa = xb; xb = tmp;
    }
}

// round 7
// speedup vs baseline: 1.6920x; 1.1540x over previous
#include <cuda_runtime.h>
#include <cuda_fp16.h>

// Fixed problem shape: U=80000, I=40000, N=120000, K=64, L=3, E=1e6
#define KF 64
#define NN 120000
#define EMAX 1000000
#define FULLMASK 0xffffffffu

typedef unsigned long long ull;

// --------------------------- device scratch (no allocs allowed) -------------
// x stored in fp16 (ping-pong); +1 zero pad row at index Nn
__device__ __align__(16) __half g_h0[(size_t)(NN + 1) * KF];
__device__ __align__(16) __half g_h1[(size_t)(NN + 1) * KF];
__device__ __align__(16) float g_side[(size_t)NN * KF];
__device__ int g_deg[NN];
__device__ int g_start[NN + 2];
__device__ int g_cursor[NN + 1];
__device__ int g_bsum[512];
__device__ __align__(16) int g_adj[2 * EMAX + 4 * NN];   // CSR padded to mult of 4

// =============================================================================
// init: e0 = l2norm(concat(Gu,Gi)) -> g_h0 (fp16) ; out[n] = rowsum/256
// extra warp (w == Nn) zeroes the pad row in both ping-pong buffers
// =============================================================================
__global__ __launch_bounds__(256) void init_kernel(
    const float* __restrict__ Gu, const float* __restrict__ Gi,
    float* __restrict__ out, int U, int Nn)
{
    int w = (blockIdx.x * blockDim.x + threadIdx.x) >> 5;
    int lane = threadIdx.x & 31;
    if (w > Nn) return;
    if (w == Nn) {
        __half2 z = __floats2half2_rn(0.f, 0.f);
        ((__half2*)(g_h0 + (size_t)Nn * KF))[lane] = z;
        ((__half2*)(g_h1 + (size_t)Nn * KF))[lane] = z;
        return;
    }
    const float* src = (w < U) ? (Gu + (size_t)w * KF) : (Gi + (size_t)(w - U) * KF);
    float2 v = ((const float2*)src)[lane];
    float ss = v.x * v.x + v.y * v.y;
    float sm = v.x + v.y;
#pragma unroll
    for (int off = 16; off >= 1; off >>= 1) {
        ss += __shfl_xor_sync(FULLMASK, ss, off);
        sm += __shfl_xor_sync(FULLMASK, sm, off);
    }
    float inv = 1.f / fmaxf(sqrtf(ss), 1e-12f);
    ((__half2*)(g_h0 + (size_t)w * KF))[lane] =
        __floats2half2_rn(v.x * inv, v.y * inv);
    if (lane == 0) { out[w] = sm * inv * (1.f / 256.f); g_deg[w] = 0; }
}

// =============================================================================
// CSR build (padded to 4): histogram -> scan of padded degrees -> fill
// =============================================================================
__global__ __launch_bounds__(256) void hist_kernel(
    const int* __restrict__ eu, const int* __restrict__ ei, int E)
{
    int idx = blockIdx.x * blockDim.x + threadIdx.x;
    if (idx >= 2 * E) return;
    int dst = (idx < E) ? eu[idx] : ei[idx - E];
    atomicAdd(&g_deg[dst], 1);
}

__global__ __launch_bounds__(256) void scan1_kernel(int Nn)
{
    int i = blockIdx.x * 256 + threadIdx.x;
    int d = (i < Nn) ? ((g_deg[i] + 3) & ~3) : 0;
    int lane = threadIdx.x & 31, wid = threadIdx.x >> 5;
    int v = d;
#pragma unroll
    for (int off = 1; off < 32; off <<= 1) {
        int t = __shfl_up_sync(FULLMASK, v, off);
        if (lane >= off) v += t;
    }
    __shared__ int wsum[8];
    if (lane == 31) wsum[wid] = v;
    __syncthreads();
    if (threadIdx.x < 8) {
        int wv = wsum[threadIdx.x];
#pragma unroll
        for (int off = 1; off < 8; off <<= 1) {
            int t = __shfl_up_sync(0xffu, wv, off);
            if ((int)threadIdx.x >= off) wv += t;
        }
        wsum[threadIdx.x] = wv;
    }
    __syncthreads();
    int woff = (wid > 0) ? wsum[wid - 1] : 0;
    if (i <= Nn) g_start[i] = woff + v - d;
    if (threadIdx.x == 0) g_bsum[blockIdx.x] = wsum[7];
}

__global__ __launch_bounds__(512) void scan2_kernel(int nb)
{
    int t = threadIdx.x;
    int lane = t & 31, wid = t >> 5;
    int d = (t < nb) ? g_bsum[t] : 0;
    int v = d;
#pragma unroll
    for (int off = 1; off < 32; off <<= 1) {
        int x = __shfl_up_sync(FULLMASK, v, off);
        if (lane >= off) v += x;
    }
    __shared__ int wsum[16];
    if (lane == 31) wsum[wid] = v;
    __syncthreads();
    if (t < 16) {
        int wv = wsum[t];
#pragma unroll
        for (int off = 1; off < 16; off <<= 1) {
            int x = __shfl_up_sync(0xffffu, wv, off);
            if (t >= off) wv += x;
        }
        wsum[t] = wv;
    }
    __syncthreads();
    int woff = (wid > 0) ? wsum[wid - 1] : 0;
    if (t < nb) g_bsum[t] = woff + v - d;  // exclusive
}

// finalize starts + cursors + write pad tails (disjoint from fill's slots)
__global__ __launch_bounds__(256) void scan3_kernel(int Nn)
{
    int i = blockIdx.x * 256 + threadIdx.x;
    if (i > Nn) return;
    int st = g_start[i] + g_bsum[blockIdx.x];
    g_start[i] = st;
    if (i < Nn) {
        g_cursor[i] = st;
        int d  = g_deg[i];
        int pd = (d + 3) & ~3;
        for (int p = d; p < pd; ++p) g_adj[st + p] = Nn;  // zero-row index
    }
}

__global__ __launch_bounds__(256) void fill_kernel(
    const int* __restrict__ eu, const int* __restrict__ ei, int E)
{
    int idx = blockIdx.x * blockDim.x + threadIdx.x;
    if (idx >= 2 * E) return;
    int dst, src;
    if (idx < E) { dst = eu[idx]; src = ei[idx]; }
    else         { dst = ei[idx - E]; src = eu[idx - E]; }
    int pos = atomicAdd(&g_cursor[dst], 1);
    g_adj[pos] = src;
}

// =============================================================================
// gather: side = A @ x (x in fp16, accumulate fp32). One warp per node,
// lane owns 2 features (__half2 = 4B per row per lane). 4 rows in flight.
// =============================================================================
__global__ __launch_bounds__(256) void gather_kernel(
    const __half* __restrict__ xin, int Nn)
{
    int node = (blockIdx.x * blockDim.x + threadIdx.x) >> 5;
    if (node >= Nn) return;
    int lane = threadIdx.x & 31;
    const __half2* xh = (const __half2*)xin;

    int a    = __ldg(g_start + node);
    int pend = __ldg(g_start + node + 1);
    float ax = 0.f, ay = 0.f;
    if (a < pend) {
        int4 A = *(const int4*)(g_adj + a);
        for (a += 4; a < pend; a += 4) {
            int4 An = *(const int4*)(g_adj + a);
            float2 v0 = __half22float2(__ldg(xh + (size_t)A.x * 32 + lane));
            float2 v1 = __half22float2(__ldg(xh + (size_t)A.y * 32 + lane));
            float2 v2 = __half22float2(__ldg(xh + (size_t)A.z * 32 + lane));
            float2 v3 = __half22float2(__ldg(xh + (size_t)A.w * 32 + lane));
            ax += (v0.x + v1.x) + (v2.x + v3.x);
            ay += (v0.y + v1.y) + (v2.y + v3.y);
            A = An;
        }
        float2 v0 = __half22float2(__ldg(xh + (size_t)A.x * 32 + lane));
        float2 v1 = __half22float2(__ldg(xh + (size_t)A.y * 32 + lane));
        float2 v2 = __half22float2(__ldg(xh + (size_t)A.z * 32 + lane));
        float2 v3 = __half22float2(__ldg(xh + (size_t)A.w * 32 + lane));
        ax += (v0.x + v1.x) + (v2.x + v3.x);
        ay += (v0.y + v1.y) + (v2.y + v3.y);
    }
    float2 o; o.x = ax; o.y = ay;
    ((float2*)(g_side + (size_t)node * KF))[lane] = o;
}

// =============================================================================
// layer: stream side(fp32)+x(fp16) -> (s,p) smem staging -> f32x2 dual-GEMM
// (lanes = W1-term/W2-term) -> leaky -> l2norm -> xout(fp16), out accumulation.
// Block = 128 threads, 64 nodes, 3 blocks/SM.
// =============================================================================
#define FMA2(d, a, b) asm("fma.rn.f32x2 %0, %1, %2, %0;" : "+l"(d) : "l"(a), "l"(b))

__device__ __forceinline__ float2 unpack2(ull v)
{
    float2 r;
    asm("mov.b64 {%0, %1}, %2;" : "=f"(r.x), "=f"(r.y) : "l"(v));
    return r;
}

#define PITCH 132                 // floats per row (128 data + 4 pad); 528B, 16B-aligned
#define SM_W12 0
#define SM_SP  (64 * PITCH)
#define LAYER_SMEM_FLOATS (2 * 64 * PITCH)
#define LAYER_SMEM_BYTES  (LAYER_SMEM_FLOATS * 4)

__global__ __launch_bounds__(128, 3) void layer_kernel(
    const __half* __restrict__ xin, __half* __restrict__ xout,
    const float* __restrict__ W1, const float* __restrict__ b1,
    const float* __restrict__ W2, const float* __restrict__ b2,
    float* __restrict__ out)
{
    extern __shared__ float smem[];
    float* sW12 = smem + SM_W12;
    float* sSP  = smem + SM_SP;

    int t = threadIdx.x;

    // stage interleaved weights: sW12[k*PITCH + 2j] = (W1[k][j], W2[k][j])
#pragma unroll
    for (int idx = t; idx < 4096; idx += 128) {
        int k = idx >> 6, j = idx & 63;
        float2 wv; wv.x = W1[idx]; wv.y = W2[idx];
        *(float2*)(sW12 + k * PITCH + 2 * j) = wv;
    }

    int base = blockIdx.x * 64;
    int w = t >> 5, lane = t & 31;
    const __half2* xh   = (const __half2*)xin;
    const float2* side2 = (const float2*)g_side;

    // ---- stage (s,p): warp handles 16 nodes, lane owns k = 2*lane, 2*lane+1
#pragma unroll 4
    for (int j = 0; j < 16; ++j) {
        int nl = w * 16 + j;
        int node = base + nl;
        float2 sv = __ldg(side2 + (size_t)node * 32 + lane);
        float2 xv = __half22float2(__ldg(xh + (size_t)node * 32 + lane));
        float4 sp;
        sp.x = sv.x + xv.x; sp.y = sv.x * xv.x;
        sp.z = sv.y + xv.y; sp.w = sv.y * xv.y;
        *(float4*)(sSP + nl * PITCH + lane * 4) = sp;
    }
    __syncthreads();

    // ---- dual GEMM: acc.lo = sum s*W1, acc.hi = sum p*W2 ----
    int jt = t & 7;       // feature lane: features jt + 8*fi
    int g  = t >> 3;      // node group: nodes 4g..4g+3

    ull acc[8][4];
#pragma unroll
    for (int fi = 0; fi < 8; ++fi)
#pragma unroll
        for (int n = 0; n < 4; ++n)
            acc[fi][n] = 0ull;

    const float* sp0 = sSP + (g * 4 + 0) * PITCH;
    const float* sp1 = sSP + (g * 4 + 1) * PITCH;
    const float* sp2 = sSP + (g * 4 + 2) * PITCH;
    const float* sp3 = sSP + (g * 4 + 3) * PITCH;
    const float* wr  = sW12 + 2 * jt;

#pragma unroll 2
    for (int k = 0; k < 64; ++k) {
        ull spv0 = *(const ull*)(sp0 + 2 * k);
        ull spv1 = *(const ull*)(sp1 + 2 * k);
        ull spv2 = *(const ull*)(sp2 + 2 * k);
        ull spv3 = *(const ull*)(sp3 + 2 * k);
        const float* wk = wr + k * PITCH;
#pragma unroll
        for (int fi = 0; fi < 8; ++fi) {
            ull wv = *(const ull*)(wk + 16 * fi);
            FMA2(acc[fi][0], spv0, wv);
            FMA2(acc[fi][1], spv1, wv);
            FMA2(acc[fi][2], spv2, wv);
            FMA2(acc[fi][3], spv3, wv);
        }
    }

    // ---- epilogue ----
#pragma unroll
    for (int n = 0; n < 4; ++n) {
        int node = base + g * 4 + n;
        float h[8];
        float ss = 0.f, sm = 0.f;
#pragma unroll
        for (int fi = 0; fi < 8; ++fi) {
            int f = jt + 8 * fi;
            float2 ab = unpack2(acc[fi][n]);
            float v = ab.x + ab.y + __ldg(b1 + f) + __ldg(b2 + f);
            v = v > 0.f ? v : 0.01f * v;
            h[fi] = v;
            ss += v * v;
            sm += v;
        }
#pragma unroll
        for (int off = 4; off >= 1; off >>= 1) {
            ss += __shfl_xor_sync(FULLMASK, ss, off);
            sm += __shfl_xor_sync(FULLMASK, sm, off);
        }
        float inv = 1.f / fmaxf(sqrtf(ss), 1e-12f);
        __half* xo = xout + (size_t)node * KF + jt;
#pragma unroll
        for (int fi = 0; fi < 8; ++fi)
            xo[8 * fi] = __float2half_rn(h[fi] * inv);
        if (jt == 0) out[node] += sm * inv * (1.f / 256.f);
    }
}

// =============================================================================
// launch: init -> CSR build -> 3 x (gather -> layer), ping-pong fp16 x buffers
// =============================================================================
extern "C" void kernel_launch(void* const* d_in, const int* in_sizes, int n_in,
                              void* d_out, int out_size)
{
    const float* Gu = (const float*)d_in[0];
    const float* Gi = (const float*)d_in[1];
    const float* W1 = (const float*)d_in[2];
    const float* b1 = (const float*)d_in[3];
    const float* W2 = (const float*)d_in[4];
    const float* b2 = (const float*)d_in[5];
    const int*   ed = (const int*)d_in[6];
    float* out = (float*)d_out;

    int U  = in_sizes[0] / KF;
    int I  = in_sizes[1] / KF;
    int Nn = U + I;
    int L  = in_sizes[3] / KF;
    int E  = in_sizes[6] / 2;
    int twoE = 2 * E;

    const int* eu = ed;
    const int* ei = ed + E;

    cudaFuncSetAttribute(layer_kernel,
                         cudaFuncAttributeMaxDynamicSharedMemorySize,
                         LAYER_SMEM_BYTES);

    __half *xa, *xb;
    cudaGetSymbolAddress((void**)&xa, g_h0);
    cudaGetSymbolAddress((void**)&xb, g_h1);

    int initBlocks = ((Nn + 1) * 32 + 255) / 256;
    init_kernel<<<initBlocks, 256>>>(Gu, Gi, out, U, Nn);

    int eBlocks = (twoE + 255) / 256;
    int nBlocks  = (Nn + 256) / 256;   // covers Nn+1 elements
    hist_kernel<<<eBlocks, 256>>>(eu, ei, E);
    scan1_kernel<<<nBlocks, 256>>>(Nn);
    scan2_kernel<<<1, 512>>>(nBlocks);
    scan3_kernel<<<nBlocks, 256>>>(Nn);
    fill_kernel<<<eBlocks, 256>>>(eu, ei, E);

    int gBlocks = (Nn * 32 + 255) / 256;
    int lBlocks = Nn / 64;  // 1875
    for (int l = 0; l < L; ++l) {
        gather_kernel<<<gBlocks, 256>>>(xa, Nn);
        layer_kernel<<<lBlocks, 128, LAYER_SMEM_BYTES>>>(
            xa, xb,
            W1 + (size_t)l * KF * KF, b1 + (size_t)l * KF,
            W2 + (size_t)l * KF * KF, b2 + (size_t)l * KF,
            out);
        __half* tmp = xa; xa = xb; xb = tmp;
    }
}

// round 8
// speedup vs baseline: 1.7027x; 1.0063x over previous
#include <cuda_runtime.h>
#include <cuda_fp16.h>

// Fixed problem shape: U=80000, I=40000, N=120000, K=64, L=3, E=1e6
#define KF 64
#define NN 120000
#define EMAX 1000000
#define FULLMASK 0xffffffffu

typedef unsigned long long ull;

// --------------------------- device scratch (no allocs allowed) -------------
// x stored in fp16 (ping-pong); +1 zero pad row at index Nn
__device__ __align__(16) __half g_h0[(size_t)(NN + 1) * KF];
__device__ __align__(16) __half g_h1[(size_t)(NN + 1) * KF];
__device__ __align__(16) float g_side[(size_t)NN * KF];
__device__ int g_deg[NN];
__device__ int g_start[NN + 2];
__device__ int g_cursor[NN + 1];
__device__ int g_bsum[512];
__device__ __align__(16) int g_adj[2 * EMAX + 4 * NN];   // CSR padded to mult of 4

// =============================================================================
// init: e0 = l2norm(concat(Gu,Gi)) -> g_h0 (fp16) ; out[n] = rowsum/256
// =============================================================================
__global__ __launch_bounds__(256) void init_kernel(
    const float* __restrict__ Gu, const float* __restrict__ Gi,
    float* __restrict__ out, int U, int Nn)
{
    int w = (blockIdx.x * blockDim.x + threadIdx.x) >> 5;
    int lane = threadIdx.x & 31;
    if (w > Nn) return;
    if (w == Nn) {
        __half2 z = __floats2half2_rn(0.f, 0.f);
        ((__half2*)(g_h0 + (size_t)Nn * KF))[lane] = z;
        ((__half2*)(g_h1 + (size_t)Nn * KF))[lane] = z;
        return;
    }
    const float* src = (w < U) ? (Gu + (size_t)w * KF) : (Gi + (size_t)(w - U) * KF);
    float2 v = ((const float2*)src)[lane];
    float ss = v.x * v.x + v.y * v.y;
    float sm = v.x + v.y;
#pragma unroll
    for (int off = 16; off >= 1; off >>= 1) {
        ss += __shfl_xor_sync(FULLMASK, ss, off);
        sm += __shfl_xor_sync(FULLMASK, sm, off);
    }
    float inv = 1.f / fmaxf(sqrtf(ss), 1e-12f);
    ((__half2*)(g_h0 + (size_t)w * KF))[lane] =
        __floats2half2_rn(v.x * inv, v.y * inv);
    if (lane == 0) { out[w] = sm * inv * (1.f / 256.f); g_deg[w] = 0; }
}

// =============================================================================
// CSR build (padded to 4): histogram -> scan of padded degrees -> fill
// =============================================================================
__global__ __launch_bounds__(256) void hist_kernel(
    const int* __restrict__ eu, const int* __restrict__ ei, int E)
{
    int idx = blockIdx.x * blockDim.x + threadIdx.x;
    if (idx >= 2 * E) return;
    int dst = (idx < E) ? eu[idx] : ei[idx - E];
    atomicAdd(&g_deg[dst], 1);
}

__global__ __launch_bounds__(256) void scan1_kernel(int Nn)
{
    int i = blockIdx.x * 256 + threadIdx.x;
    int d = (i < Nn) ? ((g_deg[i] + 3) & ~3) : 0;
    int lane = threadIdx.x & 31, wid = threadIdx.x >> 5;
    int v = d;
#pragma unroll
    for (int off = 1; off < 32; off <<= 1) {
        int t = __shfl_up_sync(FULLMASK, v, off);
        if (lane >= off) v += t;
    }
    __shared__ int wsum[8];
    if (lane == 31) wsum[wid] = v;
    __syncthreads();
    if (threadIdx.x < 8) {
        int wv = wsum[threadIdx.x];
#pragma unroll
        for (int off = 1; off < 8; off <<= 1) {
            int t = __shfl_up_sync(0xffu, wv, off);
            if ((int)threadIdx.x >= off) wv += t;
        }
        wsum[threadIdx.x] = wv;
    }
    __syncthreads();
    int woff = (wid > 0) ? wsum[wid - 1] : 0;
    if (i <= Nn) g_start[i] = woff + v - d;
    if (threadIdx.x == 0) g_bsum[blockIdx.x] = wsum[7];
}

__global__ __launch_bounds__(512) void scan2_kernel(int nb)
{
    int t = threadIdx.x;
    int lane = t & 31, wid = t >> 5;
    int d = (t < nb) ? g_bsum[t] : 0;
    int v = d;
#pragma unroll
    for (int off = 1; off < 32; off <<= 1) {
        int x = __shfl_up_sync(FULLMASK, v, off);
        if (lane >= off) v += x;
    }
    __shared__ int wsum[16];
    if (lane == 31) wsum[wid] = v;
    __syncthreads();
    if (t < 16) {
        int wv = wsum[t];
#pragma unroll
        for (int off = 1; off < 16; off <<= 1) {
            int x = __shfl_up_sync(0xffffu, wv, off);
            if (t >= off) wv += x;
        }
        wsum[t] = wv;
    }
    __syncthreads();
    int woff = (wid > 0) ? wsum[wid - 1] : 0;
    if (t < nb) g_bsum[t] = woff + v - d;  // exclusive
}

// finalize starts + cursors + write pad tails (disjoint from fill's slots)
__global__ __launch_bounds__(256) void scan3_kernel(int Nn)
{
    int i = blockIdx.x * 256 + threadIdx.x;
    if (i > Nn) return;
    int st = g_start[i] + g_bsum[blockIdx.x];
    g_start[i] = st;
    if (i < Nn) {
        g_cursor[i] = st;
        int d  = g_deg[i];
        int pd = (d + 3) & ~3;
        for (int p = d; p < pd; ++p) g_adj[st + p] = Nn;  // zero-row index
    }
}

__global__ __launch_bounds__(256) void fill_kernel(
    const int* __restrict__ eu, const int* __restrict__ ei, int E)
{
    int idx = blockIdx.x * blockDim.x + threadIdx.x;
    if (idx >= 2 * E) return;
    int dst, src;
    if (idx < E) { dst = eu[idx]; src = ei[idx]; }
    else         { dst = ei[idx - E]; src = eu[idx - E]; }
    int pos = atomicAdd(&g_cursor[dst], 1);
    g_adj[pos] = src;
}

// =============================================================================
// gather: side = A @ x (x fp16, accumulate fp32). One warp per node.
// =============================================================================
__global__ __launch_bounds__(256) void gather_kernel(
    const __half* __restrict__ xin, int Nn)
{
    int node = (blockIdx.x * blockDim.x + threadIdx.x) >> 5;
    if (node >= Nn) return;
    int lane = threadIdx.x & 31;
    const __half2* xh = (const __half2*)xin;

    int a    = __ldg(g_start + node);
    int pend = __ldg(g_start + node + 1);
    float ax = 0.f, ay = 0.f;
    if (a < pend) {
        int4 A = *(const int4*)(g_adj + a);
        for (a += 4; a < pend; a += 4) {
            int4 An = *(const int4*)(g_adj + a);
            float2 v0 = __half22float2(__ldg(xh + (size_t)A.x * 32 + lane));
            float2 v1 = __half22float2(__ldg(xh + (size_t)A.y * 32 + lane));
            float2 v2 = __half22float2(__ldg(xh + (size_t)A.z * 32 + lane));
            float2 v3 = __half22float2(__ldg(xh + (size_t)A.w * 32 + lane));
            ax += (v0.x + v1.x) + (v2.x + v3.x);
            ay += (v0.y + v1.y) + (v2.y + v3.y);
            A = An;
        }
        float2 v0 = __half22float2(__ldg(xh + (size_t)A.x * 32 + lane));
        float2 v1 = __half22float2(__ldg(xh + (size_t)A.y * 32 + lane));
        float2 v2 = __half22float2(__ldg(xh + (size_t)A.z * 32 + lane));
        float2 v3 = __half22float2(__ldg(xh + (size_t)A.w * 32 + lane));
        ax += (v0.x + v1.x) + (v2.x + v3.x);
        ay += (v0.y + v1.y) + (v2.y + v3.y);
    }
    float2 o; o.x = ax; o.y = ay;
    ((float2*)(g_side + (size_t)node * KF))[lane] = o;
}

// =============================================================================
// layer: stream side(fp32)+x(fp16) -> (s,p) staging -> f32x2 dual-GEMM
// -> leaky -> l2norm -> smem transpose -> coalesced fp16 xout, out accum.
// PITCH = 134 floats: conflict-free sp loads (rows 4 apart -> banks 8 apart).
// =============================================================================
#define FMA2(d, a, b) asm("fma.rn.f32x2 %0, %1, %2, %0;" : "+l"(d) : "l"(a), "l"(b))

__device__ __forceinline__ float2 unpack2(ull v)
{
    float2 r;
    asm("mov.b64 {%0, %1}, %2;" : "=f"(r.x), "=f"(r.y) : "l"(v));
    return r;
}

#define PITCH 134                 // floats per row; 536B (8B-aligned, banks clean)
#define SM_W12 0
#define SM_SP  (64 * PITCH)
#define LAYER_SMEM_FLOATS (2 * 64 * PITCH)
#define LAYER_SMEM_BYTES  (LAYER_SMEM_FLOATS * 4)
#define HPITCH 68                 // halves per row of output tile (136B)

__global__ __launch_bounds__(128, 3) void layer_kernel(
    const __half* __restrict__ xin, __half* __restrict__ xout,
    const float* __restrict__ W1, const float* __restrict__ b1,
    const float* __restrict__ W2, const float* __restrict__ b2,
    float* __restrict__ out)
{
    extern __shared__ float smem[];
    float* sW12 = smem + SM_W12;
    float* sSP  = smem + SM_SP;
    __half* sH  = (__half*)smem;   // reused after GEMM (behind syncthreads)

    int t = threadIdx.x;

    // stage interleaved weights: sW12[k*PITCH + 2j] = (W1[k][j], W2[k][j])
#pragma unroll
    for (int idx = t; idx < 4096; idx += 128) {
        int k = idx >> 6, j = idx & 63;
        float2 wv; wv.x = W1[idx]; wv.y = W2[idx];
        *(float2*)(sW12 + k * PITCH + 2 * j) = wv;
    }

    int base = blockIdx.x * 64;
    int w = t >> 5, lane = t & 31;
    const __half2* xh   = (const __half2*)xin;
    const float2* side2 = (const float2*)g_side;

    // ---- stage (s,p): warp handles 16 nodes, lane owns k = 2*lane, 2*lane+1
#pragma unroll 4
    for (int j = 0; j < 16; ++j) {
        int nl = w * 16 + j;
        int node = base + nl;
        float2 sv = __ldg(side2 + (size_t)node * 32 + lane);
        float2 xv = __half22float2(__ldg(xh + (size_t)node * 32 + lane));
        float2 a; a.x = sv.x + xv.x; a.y = sv.x * xv.x;
        float2 b; b.x = sv.y + xv.y; b.y = sv.y * xv.y;
        *(float2*)(sSP + nl * PITCH + lane * 4)     = a;
        *(float2*)(sSP + nl * PITCH + lane * 4 + 2) = b;
    }
    __syncthreads();

    // ---- dual GEMM: acc.lo = sum s*W1, acc.hi = sum p*W2 ----
    int jt = t & 7;       // feature lane: features jt + 8*fi
    int g  = t >> 3;      // node group: nodes 4g..4g+3

    ull acc[8][4];
#pragma unroll
    for (int fi = 0; fi < 8; ++fi)
#pragma unroll
        for (int n = 0; n < 4; ++n)
            acc[fi][n] = 0ull;

    const float* sp0 = sSP + (g * 4 + 0) * PITCH;
    const float* sp1 = sSP + (g * 4 + 1) * PITCH;
    const float* sp2 = sSP + (g * 4 + 2) * PITCH;
    const float* sp3 = sSP + (g * 4 + 3) * PITCH;
    const float* wr  = sW12 + 2 * jt;

#pragma unroll 2
    for (int k = 0; k < 64; ++k) {
        ull spv0 = *(const ull*)(sp0 + 2 * k);
        ull spv1 = *(const ull*)(sp1 + 2 * k);
        ull spv2 = *(const ull*)(sp2 + 2 * k);
        ull spv3 = *(const ull*)(sp3 + 2 * k);
        const float* wk = wr + k * PITCH;
#pragma unroll
        for (int fi = 0; fi < 8; ++fi) {
            ull wv = *(const ull*)(wk + 16 * fi);
            FMA2(acc[fi][0], spv0, wv);
            FMA2(acc[fi][1], spv1, wv);
            FMA2(acc[fi][2], spv2, wv);
            FMA2(acc[fi][3], spv3, wv);
        }
    }
    __syncthreads();   // GEMM reads done; smem can be reused as sH

    // ---- epilogue: leaky + l2norm -> sH (bank-clean), out accumulation ----
#pragma unroll
    for (int n = 0; n < 4; ++n) {
        int nl = g * 4 + n;
        float h[8];
        float ss = 0.f, sm = 0.f;
#pragma unroll
        for (int fi = 0; fi < 8; ++fi) {
            int f = jt + 8 * fi;
            float2 ab = unpack2(acc[fi][n]);
            float v = ab.x + ab.y + __ldg(b1 + f) + __ldg(b2 + f);
            v = v > 0.f ? v : 0.01f * v;
            h[fi] = v;
            ss += v * v;
            sm += v;
        }
#pragma unroll
        for (int off = 4; off >= 1; off >>= 1) {
            ss += __shfl_xor_sync(FULLMASK, ss, off);
            sm += __shfl_xor_sync(FULLMASK, sm, off);
        }
        float inv = 1.f / fmaxf(sqrtf(ss), 1e-12f);
#pragma unroll
        for (int fi = 0; fi < 8; ++fi)
            sH[nl * HPITCH + jt + 8 * fi] = __float2half_rn(h[fi] * inv);
        if (jt == 0) out[base + nl] += sm * inv * (1.f / 256.f);
    }
    __syncthreads();

    // ---- coalesced output: 64 rows x 16 uint2 (8 halves per 16B... 8B) ----
#pragma unroll
    for (int idx = t; idx < 64 * 16; idx += 128) {
        int r = idx >> 4, c = idx & 15;
        uint2 v = *(const uint2*)(sH + r * HPITCH + c * 4);
        *(uint2*)(xout + (size_t)(base + r) * KF + c * 4) = v;
    }
}

// =============================================================================
// launch
// =============================================================================
extern "C" void kernel_launch(void* const* d_in, const int* in_sizes, int n_in,
                              void* d_out, int out_size)
{
    const float* Gu = (const float*)d_in[0];
    const float* Gi = (const float*)d_in[1];
    const float* W1 = (const float*)d_in[2];
    const float* b1 = (const float*)d_in[3];
    const float* W2 = (const float*)d_in[4];
    const float* b2 = (const float*)d_in[5];
    const int*   ed = (const int*)d_in[6];
    float* out = (float*)d_out;

    int U  = in_sizes[0] / KF;
    int I  = in_sizes[1] / KF;
    int Nn = U + I;
    int L  = in_sizes[3] / KF;
    int E  = in_sizes[6] / 2;
    int twoE = 2 * E;

    const int* eu = ed;
    const int* ei = ed + E;

    cudaFuncSetAttribute(layer_kernel,
                         cudaFuncAttributeMaxDynamicSharedMemorySize,
                         LAYER_SMEM_BYTES);

    __half *xa, *xb;
    cudaGetSymbolAddress((void**)&xa, g_h0);
    cudaGetSymbolAddress((void**)&xb, g_h1);

    int initBlocks = ((Nn + 1) * 32 + 255) / 256;
    init_kernel<<<initBlocks, 256>>>(Gu, Gi, out, U, Nn);

    int eBlocks = (twoE + 255) / 256;
    int nBlocks  = (Nn + 256) / 256;   // covers Nn+1 elements
    hist_kernel<<<eBlocks, 256>>>(eu, ei, E);
    scan1_kernel<<<nBlocks, 256>>>(Nn);
    scan2_kernel<<<1, 512>>>(nBlocks);
    scan3_kernel<<<nBlocks, 256>>>(Nn);
    fill_kernel<<<eBlocks, 256>>>(eu, ei, E);

    int gBlocks = (Nn * 32 + 255) / 256;
    int lBlocks = Nn / 64;  // 1875
    for (int l = 0; l < L; ++l) {
        gather_kernel<<<gBlocks, 256>>>(xa, Nn);
        layer_kernel<<<lBlocks, 128, LAYER_SMEM_BYTES>>>(
            xa, xb,
            W1 + (size_t)l * KF * KF, b1 + (size_t)l * KF,
            W2 + (size_t)l * KF * KF, b2 + (size_t)l * KF,
            out);
        __half* tmp = xa; xa = xb; xb = tmp;
    }
}

// round 9
// speedup vs baseline: 2.5682x; 1.5083x over previous
#include <cuda_runtime.h>
#include <cuda_fp16.h>
#include <cstdint>

// Fixed problem shape: U=80000, I=40000, N=120000, K=64, L=3, E=1e6
#define KF 64
#define NN 120000
#define EMAX 1000000
#define FULLMASK 0xffffffffu

typedef unsigned long long ull;

// --------------------------- device scratch (no allocs allowed) -------------
__device__ __align__(16) __half g_h0[(size_t)(NN + 1) * KF];
__device__ __align__(16) __half g_h1[(size_t)(NN + 1) * KF];
__device__ __align__(16) float g_side[(size_t)NN * KF];
__device__ __align__(16) __half g_wh[4 * 128 * 64];     // per-layer [W1;W2] fp16
__device__ int g_deg[NN];
__device__ int g_start[NN + 2];
__device__ int g_cursor[NN + 1];
__device__ int g_bsum[512];
__device__ __align__(16) int g_adj[2 * EMAX + 4 * NN];  // CSR padded to mult of 4

// =============================================================================
// init: e0 = l2norm(concat(Gu,Gi)) -> g_h0 (fp16) ; out[n] = rowsum/256
// =============================================================================
__global__ __launch_bounds__(256) void init_kernel(
    const float* __restrict__ Gu, const float* __restrict__ Gi,
    float* __restrict__ out, int U, int Nn)
{
    int w = (blockIdx.x * blockDim.x + threadIdx.x) >> 5;
    int lane = threadIdx.x & 31;
    if (w > Nn) return;
    if (w == Nn) {
        __half2 z = __floats2half2_rn(0.f, 0.f);
        ((__half2*)(g_h0 + (size_t)Nn * KF))[lane] = z;
        ((__half2*)(g_h1 + (size_t)Nn * KF))[lane] = z;
        return;
    }
    const float* src = (w < U) ? (Gu + (size_t)w * KF) : (Gi + (size_t)(w - U) * KF);
    float2 v = ((const float2*)src)[lane];
    float ss = v.x * v.x + v.y * v.y;
    float sm = v.x + v.y;
#pragma unroll
    for (int off = 16; off >= 1; off >>= 1) {
        ss += __shfl_xor_sync(FULLMASK, ss, off);
        sm += __shfl_xor_sync(FULLMASK, sm, off);
    }
    float inv = 1.f / fmaxf(sqrtf(ss), 1e-12f);
    ((__half2*)(g_h0 + (size_t)w * KF))[lane] =
        __floats2half2_rn(v.x * inv, v.y * inv);
    if (lane == 0) { out[w] = sm * inv * (1.f / 256.f); g_deg[w] = 0; }
}

// =============================================================================
// weight convert: g_wh[l] = [[W1_l];[W2_l]] in fp16, row-major 128x64
// =============================================================================
__global__ __launch_bounds__(256) void wconv_kernel(
    const float* __restrict__ W1, const float* __restrict__ W2, int L)
{
    int i = blockIdx.x * 256 + threadIdx.x;
    if (i >= L * 4096) return;
    int l = i >> 12, rc = i & 4095;
    g_wh[l * 8192 + rc]        = __float2half_rn(W1[i]);
    g_wh[l * 8192 + 4096 + rc] = __float2half_rn(W2[i]);
}

// =============================================================================
// CSR build (padded to 4): histogram -> scan of padded degrees -> fill
// =============================================================================
__global__ __launch_bounds__(256) void hist_kernel(
    const int* __restrict__ eu, const int* __restrict__ ei, int E)
{
    int idx = blockIdx.x * blockDim.x + threadIdx.x;
    if (idx >= 2 * E) return;
    int dst = (idx < E) ? eu[idx] : ei[idx - E];
    atomicAdd(&g_deg[dst], 1);
}

__global__ __launch_bounds__(256) void scan1_kernel(int Nn)
{
    int i = blockIdx.x * 256 + threadIdx.x;
    int d = (i < Nn) ? ((g_deg[i] + 3) & ~3) : 0;
    int lane = threadIdx.x & 31, wid = threadIdx.x >> 5;
    int v = d;
#pragma unroll
    for (int off = 1; off < 32; off <<= 1) {
        int t = __shfl_up_sync(FULLMASK, v, off);
        if (lane >= off) v += t;
    }
    __shared__ int wsum[8];
    if (lane == 31) wsum[wid] = v;
    __syncthreads();
    if (threadIdx.x < 8) {
        int wv = wsum[threadIdx.x];
#pragma unroll
        for (int off = 1; off < 8; off <<= 1) {
            int t = __shfl_up_sync(0xffu, wv, off);
            if ((int)threadIdx.x >= off) wv += t;
        }
        wsum[threadIdx.x] = wv;
    }
    __syncthreads();
    int woff = (wid > 0) ? wsum[wid - 1] : 0;
    if (i <= Nn) g_start[i] = woff + v - d;
    if (threadIdx.x == 0) g_bsum[blockIdx.x] = wsum[7];
}

__global__ __launch_bounds__(512) void scan2_kernel(int nb)
{
    int t = threadIdx.x;
    int lane = t & 31, wid = t >> 5;
    int d = (t < nb) ? g_bsum[t] : 0;
    int v = d;
#pragma unroll
    for (int off = 1; off < 32; off <<= 1) {
        int x = __shfl_up_sync(FULLMASK, v, off);
        if (lane >= off) v += x;
    }
    __shared__ int wsum[16];
    if (lane == 31) wsum[wid] = v;
    __syncthreads();
    if (t < 16) {
        int wv = wsum[t];
#pragma unroll
        for (int off = 1; off < 16; off <<= 1) {
            int x = __shfl_up_sync(0xffffu, wv, off);
            if (t >= off) wv += x;
        }
        wsum[t] = wv;
    }
    __syncthreads();
    int woff = (wid > 0) ? wsum[wid - 1] : 0;
    if (t < nb) g_bsum[t] = woff + v - d;  // exclusive
}

__global__ __launch_bounds__(256) void scan3_kernel(int Nn)
{
    int i = blockIdx.x * 256 + threadIdx.x;
    if (i > Nn) return;
    int st = g_start[i] + g_bsum[blockIdx.x];
    g_start[i] = st;
    if (i < Nn) {
        g_cursor[i] = st;
        int d  = g_deg[i];
        int pd = (d + 3) & ~3;
        for (int p = d; p < pd; ++p) g_adj[st + p] = Nn;  // zero-row index
    }
}

__global__ __launch_bounds__(256) void fill_kernel(
    const int* __restrict__ eu, const int* __restrict__ ei, int E)
{
    int idx = blockIdx.x * blockDim.x + threadIdx.x;
    if (idx >= 2 * E) return;
    int dst, src;
    if (idx < E) { dst = eu[idx]; src = ei[idx]; }
    else         { dst = ei[idx - E]; src = eu[idx - E]; }
    int pos = atomicAdd(&g_cursor[dst], 1);
    g_adj[pos] = src;
}

// =============================================================================
// gather: side = A @ x (x fp16, accumulate fp32). One warp per node.
// =============================================================================
__global__ __launch_bounds__(256) void gather_kernel(
    const __half* __restrict__ xin, int Nn)
{
    int node = (blockIdx.x * blockDim.x + threadIdx.x) >> 5;
    if (node >= Nn) return;
    int lane = threadIdx.x & 31;
    const __half2* xh = (const __half2*)xin;

    int a    = __ldg(g_start + node);
    int pend = __ldg(g_start + node + 1);
    float ax = 0.f, ay = 0.f;
    if (a < pend) {
        int4 A = *(const int4*)(g_adj + a);
        for (a += 4; a < pend; a += 4) {
            int4 An = *(const int4*)(g_adj + a);
            float2 v0 = __half22float2(__ldg(xh + (size_t)A.x * 32 + lane));
            float2 v1 = __half22float2(__ldg(xh + (size_t)A.y * 32 + lane));
            float2 v2 = __half22float2(__ldg(xh + (size_t)A.z * 32 + lane));
            float2 v3 = __half22float2(__ldg(xh + (size_t)A.w * 32 + lane));
            ax += (v0.x + v1.x) + (v2.x + v3.x);
            ay += (v0.y + v1.y) + (v2.y + v3.y);
            A = An;
        }
        float2 v0 = __half22float2(__ldg(xh + (size_t)A.x * 32 + lane));
        float2 v1 = __half22float2(__ldg(xh + (size_t)A.y * 32 + lane));
        float2 v2 = __half22float2(__ldg(xh + (size_t)A.z * 32 + lane));
        float2 v3 = __half22float2(__ldg(xh + (size_t)A.w * 32 + lane));
        ax += (v0.x + v1.x) + (v2.x + v3.x);
        ay += (v0.y + v1.y) + (v2.y + v3.y);
    }
    float2 o; o.x = ax; o.y = ay;
    ((float2*)(g_side + (size_t)node * KF))[lane] = o;
}

// =============================================================================
// layer (tensor-core): A = [s|p] (64x128 fp16), B = [W1;W2] (128x64 fp16),
// C = A@B (fp32) via mma.m16n8k16; epilogue: +bias, leaky, l2norm, outputs.
// Block = 128 threads (4 warps), 64 nodes; warp w owns rows 16w..16w+15.
// =============================================================================
__device__ __forceinline__ uint32_t smem_u32(const void* p)
{
    return (uint32_t)__cvta_generic_to_shared(p);
}

__device__ __forceinline__ void ldsm_x4(uint32_t* r, uint32_t addr)
{
    asm volatile("ldmatrix.sync.aligned.m8n8.x4.shared.b16 {%0,%1,%2,%3}, [%4];"
                 : "=r"(r[0]), "=r"(r[1]), "=r"(r[2]), "=r"(r[3]) : "r"(addr));
}

__device__ __forceinline__ void ldsm_x4_t(uint32_t* r, uint32_t addr)
{
    asm volatile("ldmatrix.sync.aligned.m8n8.x4.trans.shared.b16 {%0,%1,%2,%3}, [%4];"
                 : "=r"(r[0]), "=r"(r[1]), "=r"(r[2]), "=r"(r[3]) : "r"(addr));
}

__device__ __forceinline__ void mma16816(float* d,
    uint32_t a0, uint32_t a1, uint32_t a2, uint32_t a3,
    uint32_t b0, uint32_t b1)
{
    asm volatile(
        "mma.sync.aligned.m16n8k16.row.col.f32.f16.f16.f32 "
        "{%0,%1,%2,%3}, {%4,%5,%6,%7}, {%8,%9}, {%0,%1,%2,%3};"
        : "+f"(d[0]), "+f"(d[1]), "+f"(d[2]), "+f"(d[3])
        : "r"(a0), "r"(a1), "r"(a2), "r"(a3), "r"(b0), "r"(b1));
}

#define APITCH 136   // halves per A row (272B; /4 = 68 ≡ 4 mod 32 -> LDSM clean)
#define BPITCH 72    // halves per B row (144B; /4 = 36 ≡ 4 mod 32 -> LDSM clean)

__global__ __launch_bounds__(128) void layer_kernel(
    const __half* __restrict__ xin, __half* __restrict__ xout,
    const __half* __restrict__ Wh,
    const float* __restrict__ b1, const float* __restrict__ b2,
    float* __restrict__ out)
{
    __shared__ __half sA[64 * APITCH];
    __shared__ __half sB[128 * BPITCH];
    __shared__ float sb[64];

    int t = threadIdx.x, w = t >> 5, lane = t & 31;
    int base = blockIdx.x * 64;

    // ---- stage B: 128 rows x 64 halves (uint4 = 8 halves) ----
    const uint4* wsrc = (const uint4*)Wh;   // 1024 uint4
#pragma unroll
    for (int i = t; i < 1024; i += 128) {
        int r = i >> 3, c = i & 7;
        *(uint4*)(sB + r * BPITCH + c * 8) = wsrc[i];
    }
    if (t < 64) sb[t] = b1[t] + b2[t];

    // ---- stage A: warp handles 16 nodes; lane owns k = 2*lane, 2*lane+1 ----
    const __half2* xh   = (const __half2*)xin;
    const float2* side2 = (const float2*)g_side;
#pragma unroll 4
    for (int j = 0; j < 16; ++j) {
        int nl = w * 16 + j;
        int node = base + nl;
        float2 sv = __ldg(side2 + (size_t)node * 32 + lane);
        float2 xv = __half22float2(__ldg(xh + (size_t)node * 32 + lane));
        *(__half2*)(sA + nl * APITCH + 2 * lane) =
            __floats2half2_rn(sv.x + xv.x, sv.y + xv.y);
        *(__half2*)(sA + nl * APITCH + 64 + 2 * lane) =
            __floats2half2_rn(sv.x * xv.x, sv.y * xv.y);
    }
    __syncthreads();

    // ---- MMA mainloop: M=16 (per warp), N=64, K=128 ----
    int q = lane & 7, h = lane >> 3;
    uint32_t aAddr = smem_u32(sA) +
        (uint32_t)(((16 * w + ((h & 1) << 3) + q) * APITCH + ((h >> 1) << 3)) << 1);
    uint32_t bAddr = smem_u32(sB) +
        (uint32_t)(((q + ((h & 1) << 3)) * BPITCH + ((h >> 1) << 3)) << 1);

    float acc[8][4];
#pragma unroll
    for (int nt = 0; nt < 8; ++nt)
#pragma unroll
        for (int i = 0; i < 4; ++i) acc[nt][i] = 0.f;

#pragma unroll
    for (int ks = 0; ks < 8; ++ks) {
        uint32_t a[4];
        ldsm_x4(a, aAddr + ks * 32);                    // 16 k-cols = 32B
#pragma unroll
        for (int np = 0; np < 4; ++np) {
            uint32_t b[4];
            ldsm_x4_t(b, bAddr + ks * 16 * (BPITCH * 2) + np * 32);
            mma16816(acc[np * 2],     a[0], a[1], a[2], a[3], b[0], b[1]);
            mma16816(acc[np * 2 + 1], a[0], a[1], a[2], a[3], b[2], b[3]);
        }
    }

    // ---- epilogue: +bias, leaky, row l2norm (quad reduce), outputs ----
    int cb  = (lane & 3) * 2;        // col base within n-tile
    int rlo = lane >> 2;             // 0..7
    int node_lo = base + 16 * w + rlo;
    int node_hi = node_lo + 8;

    float hlo[16], hhi[16];
    float ss_lo = 0.f, sm_lo = 0.f, ss_hi = 0.f, sm_hi = 0.f;
#pragma unroll
    for (int nt = 0; nt < 8; ++nt) {
        int col = nt * 8 + cb;
        float bb0 = sb[col], bb1 = sb[col + 1];
        float v0 = acc[nt][0] + bb0;
        float v1 = acc[nt][1] + bb1;
        float v2 = acc[nt][2] + bb0;
        float v3 = acc[nt][3] + bb1;
        v0 = v0 > 0.f ? v0 : 0.01f * v0;
        v1 = v1 > 0.f ? v1 : 0.01f * v1;
        v2 = v2 > 0.f ? v2 : 0.01f * v2;
        v3 = v3 > 0.f ? v3 : 0.01f * v3;
        hlo[2 * nt] = v0; hlo[2 * nt + 1] = v1;
        hhi[2 * nt] = v2; hhi[2 * nt + 1] = v3;
        ss_lo += v0 * v0 + v1 * v1;  sm_lo += v0 + v1;
        ss_hi += v2 * v2 + v3 * v3;  sm_hi += v2 + v3;
    }
#pragma unroll
    for (int off = 2; off >= 1; off >>= 1) {     // reduce over the quad
        ss_lo += __shfl_xor_sync(FULLMASK, ss_lo, off);
        sm_lo += __shfl_xor_sync(FULLMASK, sm_lo, off);
        ss_hi += __shfl_xor_sync(FULLMASK, ss_hi, off);
        sm_hi += __shfl_xor_sync(FULLMASK, sm_hi, off);
    }
    float inv_lo = 1.f / fmaxf(sqrtf(ss_lo), 1e-12f);
    float inv_hi = 1.f / fmaxf(sqrtf(ss_hi), 1e-12f);

    __half* xo_lo = xout + (size_t)node_lo * KF;
    __half* xo_hi = xout + (size_t)node_hi * KF;
#pragma unroll
    for (int nt = 0; nt < 8; ++nt) {
        int col = nt * 8 + cb;
        *(__half2*)(xo_lo + col) =
            __floats2half2_rn(hlo[2 * nt] * inv_lo, hlo[2 * nt + 1] * inv_lo);
        *(__half2*)(xo_hi + col) =
            __floats2half2_rn(hhi[2 * nt] * inv_hi, hhi[2 * nt + 1] * inv_hi);
    }
    if ((lane & 3) == 0) {
        out[node_lo] += sm_lo * inv_lo * (1.f / 256.f);
        out[node_hi] += sm_hi * inv_hi * (1.f / 256.f);
    }
}

// =============================================================================
// launch: init + wconv -> CSR build -> 3 x (gather -> layer)
// =============================================================================
extern "C" void kernel_launch(void* const* d_in, const int* in_sizes, int n_in,
                              void* d_out, int out_size)
{
    const float* Gu = (const float*)d_in[0];
    const float* Gi = (const float*)d_in[1];
    const float* W1 = (const float*)d_in[2];
    const float* b1 = (const float*)d_in[3];
    const float* W2 = (const float*)d_in[4];
    const float* b2 = (const float*)d_in[5];
    const int*   ed = (const int*)d_in[6];
    float* out = (float*)d_out;

    int U  = in_sizes[0] / KF;
    int I  = in_sizes[1] / KF;
    int Nn = U + I;
    int L  = in_sizes[3] / KF;
    int E  = in_sizes[6] / 2;
    int twoE = 2 * E;

    const int* eu = ed;
    const int* ei = ed + E;

    __half *xa, *xb, *wh;
    cudaGetSymbolAddress((void**)&xa, g_h0);
    cudaGetSymbolAddress((void**)&xb, g_h1);
    cudaGetSymbolAddress((void**)&wh, g_wh);

    int initBlocks = ((Nn + 1) * 32 + 255) / 256;
    init_kernel<<<initBlocks, 256>>>(Gu, Gi, out, U, Nn);
    wconv_kernel<<<(L * 4096 + 255) / 256, 256>>>(W1, W2, L);

    int eBlocks = (twoE + 255) / 256;
    int nBlocks = (Nn + 256) / 256;   // covers Nn+1 elements
    hist_kernel<<<eBlocks, 256>>>(eu, ei, E);
    scan1_kernel<<<nBlocks, 256>>>(Nn);
    scan2_kernel<<<1, 512>>>(nBlocks);
    scan3_kernel<<<nBlocks, 256>>>(Nn);
    fill_kernel<<<eBlocks, 256>>>(eu, ei, E);

    int gBlocks = (Nn * 32 + 255) / 256;
    int lBlocks = Nn / 64;  // 1875
    for (int l = 0; l < L; ++l) {
        gather_kernel<<<gBlocks, 256>>>(xa, Nn);
        layer_kernel<<<lBlocks, 128>>>(
            xa, xb, wh + (size_t)l * 8192,
            b1 + (size_t)l * KF, b2 + (size_t)l * KF, out);
        __half* tmp = xa; xa = xb; xb = tmp;
    }
}

// round 10
// speedup vs baseline: 2.6416x; 1.0286x over previous
#include <cuda_runtime.h>
#include <cuda_fp16.h>
#include <cstdint>

// Fixed problem shape: U=80000, I=40000, N=120000, K=64, L=3, E=1e6
#define KF 64
#define NN 120000
#define EMAX 1000000
#define FULLMASK 0xffffffffu

typedef unsigned long long ull;

// --------------------------- device scratch (no allocs allowed) -------------
__device__ __align__(16) __half g_h0[(size_t)(NN + 1) * KF];
__device__ __align__(16) __half g_h1[(size_t)(NN + 1) * KF];
__device__ __align__(16) __half g_side[(size_t)NN * KF];
__device__ __align__(16) __half g_wh[4 * 128 * 64];     // per-layer [W1;W2] fp16
__device__ int g_deg[NN];
__device__ int g_start[NN + 2];
__device__ int g_cursor[NN + 1];
__device__ int g_bsum[512];
__device__ __align__(16) int g_adj[2 * EMAX + 4 * NN];  // CSR padded to mult of 4

// =============================================================================
// init: e0 = l2norm(concat(Gu,Gi)) -> g_h0 (fp16) ; out[n] = rowsum/256
// =============================================================================
__global__ __launch_bounds__(256) void init_kernel(
    const float* __restrict__ Gu, const float* __restrict__ Gi,
    float* __restrict__ out, int U, int Nn)
{
    int w = (blockIdx.x * blockDim.x + threadIdx.x) >> 5;
    int lane = threadIdx.x & 31;
    if (w > Nn) return;
    if (w == Nn) {
        __half2 z = __floats2half2_rn(0.f, 0.f);
        ((__half2*)(g_h0 + (size_t)Nn * KF))[lane] = z;
        ((__half2*)(g_h1 + (size_t)Nn * KF))[lane] = z;
        return;
    }
    const float* src = (w < U) ? (Gu + (size_t)w * KF) : (Gi + (size_t)(w - U) * KF);
    float2 v = ((const float2*)src)[lane];
    float ss = v.x * v.x + v.y * v.y;
    float sm = v.x + v.y;
#pragma unroll
    for (int off = 16; off >= 1; off >>= 1) {
        ss += __shfl_xor_sync(FULLMASK, ss, off);
        sm += __shfl_xor_sync(FULLMASK, sm, off);
    }
    float inv = 1.f / fmaxf(sqrtf(ss), 1e-12f);
    ((__half2*)(g_h0 + (size_t)w * KF))[lane] =
        __floats2half2_rn(v.x * inv, v.y * inv);
    if (lane == 0) { out[w] = sm * inv * (1.f / 256.f); g_deg[w] = 0; }
}

// =============================================================================
// weight convert: g_wh[l] = [[W1_l];[W2_l]] in fp16, row-major 128x64
// =============================================================================
__global__ __launch_bounds__(256) void wconv_kernel(
    const float* __restrict__ W1, const float* __restrict__ W2, int L)
{
    int i = blockIdx.x * 256 + threadIdx.x;
    if (i >= L * 4096) return;
    int l = i >> 12, rc = i & 4095;
    g_wh[l * 8192 + rc]        = __float2half_rn(W1[i]);
    g_wh[l * 8192 + 4096 + rc] = __float2half_rn(W2[i]);
}

// =============================================================================
// CSR build (padded to 4): histogram -> scan of padded degrees -> fill
// =============================================================================
__global__ __launch_bounds__(256) void hist_kernel(
    const int* __restrict__ eu, const int* __restrict__ ei, int E)
{
    int idx = blockIdx.x * blockDim.x + threadIdx.x;
    if (idx >= 2 * E) return;
    int dst = (idx < E) ? eu[idx] : ei[idx - E];
    atomicAdd(&g_deg[dst], 1);
}

__global__ __launch_bounds__(256) void scan1_kernel(int Nn)
{
    int i = blockIdx.x * 256 + threadIdx.x;
    int d = (i < Nn) ? ((g_deg[i] + 3) & ~3) : 0;
    int lane = threadIdx.x & 31, wid = threadIdx.x >> 5;
    int v = d;
#pragma unroll
    for (int off = 1; off < 32; off <<= 1) {
        int t = __shfl_up_sync(FULLMASK, v, off);
        if (lane >= off) v += t;
    }
    __shared__ int wsum[8];
    if (lane == 31) wsum[wid] = v;
    __syncthreads();
    if (threadIdx.x < 8) {
        int wv = wsum[threadIdx.x];
#pragma unroll
        for (int off = 1; off < 8; off <<= 1) {
            int t = __shfl_up_sync(0xffu, wv, off);
            if ((int)threadIdx.x >= off) wv += t;
        }
        wsum[threadIdx.x] = wv;
    }
    __syncthreads();
    int woff = (wid > 0) ? wsum[wid - 1] : 0;
    if (i <= Nn) g_start[i] = woff + v - d;
    if (threadIdx.x == 0) g_bsum[blockIdx.x] = wsum[7];
}

__global__ __launch_bounds__(512) void scan2_kernel(int nb)
{
    int t = threadIdx.x;
    int lane = t & 31, wid = t >> 5;
    int d = (t < nb) ? g_bsum[t] : 0;
    int v = d;
#pragma unroll
    for (int off = 1; off < 32; off <<= 1) {
        int x = __shfl_up_sync(FULLMASK, v, off);
        if (lane >= off) v += x;
    }
    __shared__ int wsum[16];
    if (lane == 31) wsum[wid] = v;
    __syncthreads();
    if (t < 16) {
        int wv = wsum[t];
#pragma unroll
        for (int off = 1; off < 16; off <<= 1) {
            int x = __shfl_up_sync(0xffffu, wv, off);
            if (t >= off) wv += x;
        }
        wsum[t] = wv;
    }
    __syncthreads();
    int woff = (wid > 0) ? wsum[wid - 1] : 0;
    if (t < nb) g_bsum[t] = woff + v - d;  // exclusive
}

__global__ __launch_bounds__(256) void scan3_kernel(int Nn)
{
    int i = blockIdx.x * 256 + threadIdx.x;
    if (i > Nn) return;
    int st = g_start[i] + g_bsum[blockIdx.x];
    g_start[i] = st;
    if (i < Nn) {
        g_cursor[i] = st;
        int d  = g_deg[i];
        int pd = (d + 3) & ~3;
        for (int p = d; p < pd; ++p) g_adj[st + p] = Nn;  // zero-row index
    }
}

__global__ __launch_bounds__(256) void fill_kernel(
    const int* __restrict__ eu, const int* __restrict__ ei, int E)
{
    int idx = blockIdx.x * blockDim.x + threadIdx.x;
    if (idx >= 2 * E) return;
    int dst, src;
    if (idx < E) { dst = eu[idx]; src = ei[idx]; }
    else         { dst = ei[idx - E]; src = eu[idx - E]; }
    int pos = atomicAdd(&g_cursor[dst], 1);
    g_adj[pos] = src;
}

// =============================================================================
// gather: side = A @ x (x fp16, accumulate fp32, store fp16). Warp per node.
// =============================================================================
__global__ __launch_bounds__(256) void gather_kernel(
    const __half* __restrict__ xin, int Nn)
{
    int node = (blockIdx.x * blockDim.x + threadIdx.x) >> 5;
    if (node >= Nn) return;
    int lane = threadIdx.x & 31;
    const __half2* xh = (const __half2*)xin;

    int a    = __ldg(g_start + node);
    int pend = __ldg(g_start + node + 1);
    float ax = 0.f, ay = 0.f;
    if (a < pend) {
        int4 A = *(const int4*)(g_adj + a);
        for (a += 4; a < pend; a += 4) {
            int4 An = *(const int4*)(g_adj + a);
            float2 v0 = __half22float2(__ldg(xh + (size_t)A.x * 32 + lane));
            float2 v1 = __half22float2(__ldg(xh + (size_t)A.y * 32 + lane));
            float2 v2 = __half22float2(__ldg(xh + (size_t)A.z * 32 + lane));
            float2 v3 = __half22float2(__ldg(xh + (size_t)A.w * 32 + lane));
            ax += (v0.x + v1.x) + (v2.x + v3.x);
            ay += (v0.y + v1.y) + (v2.y + v3.y);
            A = An;
        }
        float2 v0 = __half22float2(__ldg(xh + (size_t)A.x * 32 + lane));
        float2 v1 = __half22float2(__ldg(xh + (size_t)A.y * 32 + lane));
        float2 v2 = __half22float2(__ldg(xh + (size_t)A.z * 32 + lane));
        float2 v3 = __half22float2(__ldg(xh + (size_t)A.w * 32 + lane));
        ax += (v0.x + v1.x) + (v2.x + v3.x);
        ay += (v0.y + v1.y) + (v2.y + v3.y);
    }
    ((__half2*)(g_side + (size_t)node * KF))[lane] = __floats2half2_rn(ax, ay);
}

// =============================================================================
// layer (tensor-core, 128 nodes/block): A = [s|p] (128x128 fp16),
// B = [W1;W2] (128x64 fp16), C = A@B fp32 via mma.m16n8k16.
// 256 threads = 8 warps; warp w owns rows 16w..16w+15. Dynamic smem 53.5KB.
// =============================================================================
__device__ __forceinline__ uint32_t smem_u32(const void* p)
{
    return (uint32_t)__cvta_generic_to_shared(p);
}

__device__ __forceinline__ void ldsm_x4(uint32_t* r, uint32_t addr)
{
    asm volatile("ldmatrix.sync.aligned.m8n8.x4.shared.b16 {%0,%1,%2,%3}, [%4];"
                 : "=r"(r[0]), "=r"(r[1]), "=r"(r[2]), "=r"(r[3]) : "r"(addr));
}

__device__ __forceinline__ void ldsm_x4_t(uint32_t* r, uint32_t addr)
{
    asm volatile("ldmatrix.sync.aligned.m8n8.x4.trans.shared.b16 {%0,%1,%2,%3}, [%4];"
                 : "=r"(r[0]), "=r"(r[1]), "=r"(r[2]), "=r"(r[3]) : "r"(addr));
}

__device__ __forceinline__ void mma16816(float* d,
    uint32_t a0, uint32_t a1, uint32_t a2, uint32_t a3,
    uint32_t b0, uint32_t b1)
{
    asm volatile(
        "mma.sync.aligned.m16n8k16.row.col.f32.f16.f16.f32 "
        "{%0,%1,%2,%3}, {%4,%5,%6,%7}, {%8,%9}, {%0,%1,%2,%3};"
        : "+f"(d[0]), "+f"(d[1]), "+f"(d[2]), "+f"(d[3])
        : "r"(a0), "r"(a1), "r"(a2), "r"(a3), "r"(b0), "r"(b1));
}

#define APITCH 136   // halves per A row (272B; /4 = 68 ≡ 4 mod 32 -> LDSM clean)
#define BPITCH 72    // halves per B row (144B; /4 = 36 ≡ 4 mod 32 -> LDSM clean)
#define LNODES 128
// dynamic smem: sA 128*136*2 + sB 128*72*2 + sb 64*4 = 34816+18432+256 = 53504
#define LAYER_SMEM_BYTES (LNODES * APITCH * 2 + 128 * BPITCH * 2 + 256)

__global__ __launch_bounds__(256, 4) void layer_kernel(
    const __half* __restrict__ xin, __half* __restrict__ xout,
    const __half* __restrict__ Wh,
    const float* __restrict__ b1, const float* __restrict__ b2,
    float* __restrict__ out, int Nn)
{
    extern __shared__ __half smh[];
    __half* sA = smh;                       // 128 x APITCH
    __half* sB = smh + LNODES * APITCH;     // 128 x BPITCH
    float*  sb = (float*)(sB + 128 * BPITCH);

    int t = threadIdx.x, w = t >> 5, lane = t & 31;
    int base = blockIdx.x * LNODES;

    // ---- stage B: 128 rows x 64 halves (uint4 = 8 halves) ----
    const uint4* wsrc = (const uint4*)Wh;   // 1024 uint4
#pragma unroll
    for (int i = t; i < 1024; i += 256) {
        int r = i >> 3, c = i & 7;
        *(uint4*)(sB + r * BPITCH + c * 8) = wsrc[i];
    }
    if (t < 64) sb[t] = b1[t] + b2[t];

    // ---- stage A: warp handles 16 nodes; lane owns k = 2*lane, 2*lane+1 ----
    const __half2* xh   = (const __half2*)xin;
    const __half2* sd2  = (const __half2*)g_side;
#pragma unroll 4
    for (int j = 0; j < 16; ++j) {
        int nl = w * 16 + j;
        int node = base + nl;
        __half2 s, p;
        if (node < Nn) {
            __half2 sv = __ldg(sd2 + (size_t)node * 32 + lane);
            __half2 xv = __ldg(xh  + (size_t)node * 32 + lane);
            s = __hadd2(sv, xv);
            p = __hmul2(sv, xv);
        } else {
            s = __floats2half2_rn(0.f, 0.f);
            p = s;
        }
        *(__half2*)(sA + nl * APITCH + 2 * lane)      = s;
        *(__half2*)(sA + nl * APITCH + 64 + 2 * lane) = p;
    }
    __syncthreads();

    // ---- MMA mainloop: M=16 (per warp), N=64, K=128 ----
    int q = lane & 7, h = lane >> 3;
    uint32_t aAddr = smem_u32(sA) +
        (uint32_t)(((16 * w + ((h & 1) << 3) + q) * APITCH + ((h >> 1) << 3)) << 1);
    uint32_t bAddr = smem_u32(sB) +
        (uint32_t)(((q + ((h & 1) << 3)) * BPITCH + ((h >> 1) << 3)) << 1);

    float acc[8][4];
#pragma unroll
    for (int nt = 0; nt < 8; ++nt)
#pragma unroll
        for (int i = 0; i < 4; ++i) acc[nt][i] = 0.f;

#pragma unroll
    for (int ks = 0; ks < 8; ++ks) {
        uint32_t a[4];
        ldsm_x4(a, aAddr + ks * 32);                    // 16 k-cols = 32B
#pragma unroll
        for (int np = 0; np < 4; ++np) {
            uint32_t b[4];
            ldsm_x4_t(b, bAddr + ks * 16 * (BPITCH * 2) + np * 32);
            mma16816(acc[np * 2],     a[0], a[1], a[2], a[3], b[0], b[1]);
            mma16816(acc[np * 2 + 1], a[0], a[1], a[2], a[3], b[2], b[3]);
        }
    }

    // ---- epilogue: +bias, leaky, row l2norm (quad reduce), outputs ----
    // acc registers are reused in place to keep reg count <= 64.
    int cb  = (lane & 3) * 2;        // col base within n-tile
    int rlo = lane >> 2;             // 0..7
    int node_lo = base + 16 * w + rlo;
    int node_hi = node_lo + 8;

    float ss_lo = 0.f, sm_lo = 0.f, ss_hi = 0.f, sm_hi = 0.f;
#pragma unroll
    for (int nt = 0; nt < 8; ++nt) {
        int col = nt * 8 + cb;
        float bb0 = sb[col], bb1 = sb[col + 1];
        float v0 = acc[nt][0] + bb0;
        float v1 = acc[nt][1] + bb1;
        float v2 = acc[nt][2] + bb0;
        float v3 = acc[nt][3] + bb1;
        v0 = v0 > 0.f ? v0 : 0.01f * v0;
        v1 = v1 > 0.f ? v1 : 0.01f * v1;
        v2 = v2 > 0.f ? v2 : 0.01f * v2;
        v3 = v3 > 0.f ? v3 : 0.01f * v3;
        acc[nt][0] = v0; acc[nt][1] = v1; acc[nt][2] = v2; acc[nt][3] = v3;
        ss_lo += v0 * v0 + v1 * v1;  sm_lo += v0 + v1;
        ss_hi += v2 * v2 + v3 * v3;  sm_hi += v2 + v3;
    }
#pragma unroll
    for (int off = 2; off >= 1; off >>= 1) {     // reduce over the quad
        ss_lo += __shfl_xor_sync(FULLMASK, ss_lo, off);
        sm_lo += __shfl_xor_sync(FULLMASK, sm_lo, off);
        ss_hi += __shfl_xor_sync(FULLMASK, ss_hi, off);
        sm_hi += __shfl_xor_sync(FULLMASK, sm_hi, off);
    }
    float inv_lo = 1.f / fmaxf(sqrtf(ss_lo), 1e-12f);
    float inv_hi = 1.f / fmaxf(sqrtf(ss_hi), 1e-12f);

    if (node_lo < Nn) {
        __half* xo = xout + (size_t)node_lo * KF;
#pragma unroll
        for (int nt = 0; nt < 8; ++nt)
            *(__half2*)(xo + nt * 8 + cb) =
                __floats2half2_rn(acc[nt][0] * inv_lo, acc[nt][1] * inv_lo);
        if ((lane & 3) == 0) out[node_lo] += sm_lo * inv_lo * (1.f / 256.f);
    }
    if (node_hi < Nn) {
        __half* xo = xout + (size_t)node_hi * KF;
#pragma unroll
        for (int nt = 0; nt < 8; ++nt)
            *(__half2*)(xo + nt * 8 + cb) =
                __floats2half2_rn(acc[nt][2] * inv_hi, acc[nt][3] * inv_hi);
        if ((lane & 3) == 0) out[node_hi] += sm_hi * inv_hi * (1.f / 256.f);
    }
}

// =============================================================================
// launch: init + wconv -> CSR build -> 3 x (gather -> layer)
// =============================================================================
extern "C" void kernel_launch(void* const* d_in, const int* in_sizes, int n_in,
                              void* d_out, int out_size)
{
    const float* Gu = (const float*)d_in[0];
    const float* Gi = (const float*)d_in[1];
    const float* W1 = (const float*)d_in[2];
    const float* b1 = (const float*)d_in[3];
    const float* W2 = (const float*)d_in[4];
    const float* b2 = (const float*)d_in[5];
    const int*   ed = (const int*)d_in[6];
    float* out = (float*)d_out;

    int U  = in_sizes[0] / KF;
    int I  = in_sizes[1] / KF;
    int Nn = U + I;
    int L  = in_sizes[3] / KF;
    int E  = in_sizes[6] / 2;
    int twoE = 2 * E;

    const int* eu = ed;
    const int* ei = ed + E;

    cudaFuncSetAttribute(layer_kernel,
                         cudaFuncAttributeMaxDynamicSharedMemorySize,
                         LAYER_SMEM_BYTES);

    __half *xa, *xb, *wh;
    cudaGetSymbolAddress((void**)&xa, g_h0);
    cudaGetSymbolAddress((void**)&xb, g_h1);
    cudaGetSymbolAddress((void**)&wh, g_wh);

    int initBlocks = ((Nn + 1) * 32 + 255) / 256;
    init_kernel<<<initBlocks, 256>>>(Gu, Gi, out, U, Nn);
    wconv_kernel<<<(L * 4096 + 255) / 256, 256>>>(W1, W2, L);

    int eBlocks = (twoE + 255) / 256;
    int nBlocks = (Nn + 256) / 256;   // covers Nn+1 elements
    hist_kernel<<<eBlocks, 256>>>(eu, ei, E);
    scan1_kernel<<<nBlocks, 256>>>(Nn);
    scan2_kernel<<<1, 512>>>(nBlocks);
    scan3_kernel<<<nBlocks, 256>>>(Nn);
    fill_kernel<<<eBlocks, 256>>>(eu, ei, E);

    int gBlocks = (Nn * 32 + 255) / 256;
    int lBlocks = (Nn + LNODES - 1) / LNODES;   // 938
    for (int l = 0; l < L; ++l) {
        gather_kernel<<<gBlocks, 256>>>(xa, Nn);
        layer_kernel<<<lBlocks, 256, LAYER_SMEM_BYTES>>>(
            xa, xb, wh + (size_t)l * 8192,
            b1 + (size_t)l * KF, b2 + (size_t)l * KF, out, Nn);
        __half* tmp = xa; xa = xb; xb = tmp;
    }
}